// round 9
// baseline (speedup 1.0000x reference)
#include <cuda_runtime.h>
#include <math.h>

#define DD 1024
#define GBK 16

// ---------------- static device storage (no allocation allowed) ----------------
static __device__ double d_H[32 * 32];
static __device__ double d_g;
static __device__ double d_CS[DD * DD];
static __device__ double d_CA[DD * DD];
static __device__ float  d_M0[DD * DD];     // P
static __device__ float  d_M1[DD * DD];     // P2 / E / U
static __device__ float  d_M2[DD * DD];     // P3
static __device__ float  d_M3[DD * DD];     // W / ping
static __device__ float  d_M4[DD * DD];     // P4
static __device__ float  d_ua[DD];
static __device__ float  d_ub[DD];
static __device__ float  d_Arows[2048 * DD];

// ---------------- model: H on reduced 32-dim space ----------------
__device__ __forceinline__ double qmat(int r, int c) {
    if (c == r + 1) return sqrt((double)c * 0.5);
    if (r == c + 1) return sqrt((double)r * 0.5);
    return 0.0;
}

__global__ void k_build_H(const float* log_g) {
    int a = threadIdx.x;
    if (a == 0) d_g = (double)expf(log_g[0]);
    int i = a >> 5, j = a & 31;
    int si = i >> 4, vi = i & 15, v6i = vi >> 2, v10i = vi & 3;
    int sj = j >> 4, vj = j & 15, v6j = vj >> 2, v10j = vj & 3;
    const double CM2EV = 0.00012398419;
    const double E_S1 = 3.995, E_S2 = 4.9183;
    const double om6a = 596.0 * CM2EV, om10a = 919.0 * CM2EV;
    const double kap1 = -0.0964, kap2 = 0.1193;
    const double lam = 0.1825, gam = -0.018;
    double val = 0.0;
    if (si == sj) {
        if (vi == vj) val += (si == 0 ? E_S1 : E_S2) + om6a * v6i + om10a * v10i;
        if (v10i == v10j) val += (si == 0 ? kap1 : kap2) * qmat(v6i, v6j);
    } else {
        if (v6i == v6j) {
            double q2 = 0.0;
            #pragma unroll
            for (int m = 0; m < 4; m++) q2 += qmat(v10i, m) * qmat(m, v10j);
            val += lam * qmat(v10i, v10j) + gam * q2;
        }
    }
    d_H[i * 32 + j] = val;
}

// ---------------- real hermitian basis bookkeeping ----------------
__device__ __forceinline__ void decode_basis(int m, int& type, int& p, int& q) {
    if (m < 32) { type = 0; p = q = m; return; }
    int pi = (m < 528) ? (m - 32) : (m - 528);
    type = (m < 528) ? 1 : 2;
    int r = 0, cnt = 31;
    while (pi >= cnt) { pi -= cnt; r++; cnt--; }
    p = r; q = r + 1 + pi;
}

__global__ void k_stageG() {
    int n = blockIdx.x;
    int ab = threadIdx.x;
    int a = ab >> 5, b = ab & 31;
    int type, p, q;
    decode_basis(n, type, p, q);
    double v = (type == 0) ? 1.0 : 0.70710678118654752440;
    int nc = (type == 0) ? 1 : 2;
    int cc[2] = { p, q };
    int dd[2] = { q, p };
    double ww[2] = { v, (type == 2) ? -v : v };

    const double g = d_g;
    double HX = 0.0, XH = 0.0, Xab = 0.0, X16 = 0.0;
    for (int e = 0; e < nc; e++) {
        if (dd[e] == b) HX += d_H[a * 32 + cc[e]] * ww[e];
        if (cc[e] == a) XH += ww[e] * d_H[dd[e] * 32 + b];
        if (cc[e] == a && dd[e] == b) Xab += ww[e];
        if (a < 16 && b < 16 && cc[e] == a + 16 && dd[e] == b + 16) X16 += ww[e];
    }
    double diss = g * (X16 - 0.5 * Xab * (double)((a >= 16) + (b >= 16)));
    double cs, ca;
    if (type == 2) { cs = XH - HX; ca = diss; }
    else           { ca = HX - XH; cs = diss; }
    d_CS[n * DD + ab] = cs;
    d_CA[n * DD + ab] = ca;
}

// scale = (DT/HBAR) / 2^2   (s = 2 squarings for expm, order-8 Taylor)
__global__ void k_project() {
    int idx = blockIdx.x * 1024 + threadIdx.x;
    int m = idx >> 10, n = idx & 1023;
    int type, i, j;
    decode_basis(m, type, i, j);
    const double SQ2 = 1.41421356237309504880;
    double val;
    if (type == 0)      val = d_CS[n * DD + i * 33];
    else if (type == 1) val = SQ2 * d_CS[n * DD + i * 32 + j];
    else                val = SQ2 * d_CA[n * DD + i * 32 + j];
    const double scale = (1.0 / 0.6582119569) / 4.0;
    d_M0[m * DD + n] = (float)(val * scale);
}

__global__ void k_Ainit() {
    int r = blockIdx.x, c = threadIdx.x;
    float v = 0.0f;
    if (r == 0 && c < 16) v = 1.0f;
    if (r == 1 && c >= 16 && c < 32) v = 1.0f;
    d_Arows[r * DD + c] = v;
}

__global__ void k_extract(float* __restrict__ out, int n) {
    int t = blockIdx.x * blockDim.x + threadIdx.x;
    if (t >= n) return;
    out[t] = 0.0f;
    out[n + t]     = d_Arows[(size_t)(2 * t) * DD + 16];
    out[2 * n + t] = d_Arows[(size_t)(2 * t + 1) * DD + 16];
}

// ---------------- packed f32x2 helpers ----------------
__device__ __forceinline__ void ffma2(unsigned long long& acc,
                                      unsigned long long a, unsigned long long b) {
    asm("fma.rn.f32x2 %0, %1, %2, %0;" : "+l"(acc) : "l"(a), "l"(b));
}
__device__ __forceinline__ unsigned long long pack2(float x) {
    unsigned long long r; unsigned u = __float_as_uint(x);
    asm("mov.b64 %0, {%1, %1};" : "=l"(r) : "r"(u));
    return r;
}
__device__ __forceinline__ void unpack2(unsigned long long v, float& lo, float& hi) {
    unsigned a, b;
    asm("mov.b64 {%0, %1}, %2;" : "=r"(a), "=r"(b) : "l"(v));
    lo = __uint_as_float(a); hi = __uint_as_float(b);
}

// ---------------- GEMM: C(MxDD)=A@B; 128x64 tile; 512 thr = 2 K-teams of 256 ----------------
// Micro-tile 4 rows x 8 cols; warp spans tx 0..7, ty 0..3 -> sB LDS.128 = 1 wavefront.
// Team 0 sums k in [0,512), team 1 in [512,1024); deterministic lo+hi combine via pad.
// mode 0: C = v
// mode 1: C(=P4) = v;  W = I/24 + P/120 + P2/720 + P3/5040 + v/40320
// mode 2: C(=E)  = v + I + P + P2/2 + P3/6
__device__ __forceinline__ void gemm_tile(
    const float* __restrict__ A, const float* __restrict__ B, float* __restrict__ C,
    int M, int row0, int bx, int mode,
    const float* __restrict__ P, const float* __restrict__ P2,
    const float* __restrict__ P3, float* __restrict__ W)
{
    __shared__ float smem[8192];              // 32KB: 2 teams x (sA 16x128 + sB 16x64); pad alias
    int tid = threadIdx.x;
    int team = tid >> 8;
    int t = tid & 255;
    int tx = t & 7;                           // col group (8 cols each)
    int ty = t >> 3;                          // row group (4 rows each), 0..31
    int k0 = team << 9;
    float* sA = smem + team * 3072;           // [16][128]
    float* sB = smem + team * 3072 + 2048;    // [16][64]
    float* pad = smem;                        // 128x64 partial pad (alias, used after final sync)

    unsigned long long acc[4][4];
    #pragma unroll
    for (int i = 0; i < 4; i++)
        #pragma unroll
        for (int j = 0; j < 4; j++) acc[i][j] = 0ULL;

    for (int kt = 0; kt < 512; kt += GBK) {
        #pragma unroll
        for (int u = 0; u < 2; u++) {         // stage A (transposed): 512 float4s / 256 thr
            int e = t + 256 * u;
            int r = e >> 2, kc = e & 3;
            float4 v = make_float4(0.f, 0.f, 0.f, 0.f);
            if (row0 + r < M)
                v = *(const float4*)&A[(size_t)(row0 + r) * DD + k0 + kt + kc * 4];
            sA[(kc * 4 + 0) * 128 + r] = v.x;
            sA[(kc * 4 + 1) * 128 + r] = v.y;
            sA[(kc * 4 + 2) * 128 + r] = v.z;
            sA[(kc * 4 + 3) * 128 + r] = v.w;
        }
        {   // stage B: 256 float4s / 256 thr
            int k = t >> 4, c = t & 15;
            *(float4*)&sB[k * 64 + c * 4] =
                *(const float4*)&B[(size_t)(k0 + kt + k) * DD + bx * 64 + c * 4];
        }
        __syncthreads();
        #pragma unroll
        for (int kk = 0; kk < GBK; kk++) {
            float4 av = *(const float4*)&sA[kk * 128 + ty * 4];
            ulonglong2 b01 = *(const ulonglong2*)&sB[kk * 64 + tx * 8];
            ulonglong2 b23 = *(const ulonglong2*)&sB[kk * 64 + tx * 8 + 4];
            unsigned long long a0 = pack2(av.x), a1 = pack2(av.y),
                               a2 = pack2(av.z), a3 = pack2(av.w);
            ffma2(acc[0][0], a0, b01.x); ffma2(acc[0][1], a0, b01.y);
            ffma2(acc[0][2], a0, b23.x); ffma2(acc[0][3], a0, b23.y);
            ffma2(acc[1][0], a1, b01.x); ffma2(acc[1][1], a1, b01.y);
            ffma2(acc[1][2], a1, b23.x); ffma2(acc[1][3], a1, b23.y);
            ffma2(acc[2][0], a2, b01.x); ffma2(acc[2][1], a2, b01.y);
            ffma2(acc[2][2], a2, b23.x); ffma2(acc[2][3], a2, b23.y);
            ffma2(acc[3][0], a3, b01.x); ffma2(acc[3][1], a3, b01.y);
            ffma2(acc[3][2], a3, b23.x); ffma2(acc[3][3], a3, b23.y);
        }
        __syncthreads();
    }

    // combine: team 1 deposits partials; team 0 adds (deterministic lo-half + hi-half)
    if (team == 1) {
        #pragma unroll
        for (int i = 0; i < 4; i++) {
            float v[8];
            unpack2(acc[i][0], v[0], v[1]);
            unpack2(acc[i][1], v[2], v[3]);
            unpack2(acc[i][2], v[4], v[5]);
            unpack2(acc[i][3], v[6], v[7]);
            int rl = ty * 4 + i;
            *(float4*)&pad[rl * 64 + tx * 8]     = make_float4(v[0], v[1], v[2], v[3]);
            *(float4*)&pad[rl * 64 + tx * 8 + 4] = make_float4(v[4], v[5], v[6], v[7]);
        }
    }
    __syncthreads();
    if (team == 0) {
        #pragma unroll
        for (int i = 0; i < 4; i++) {
            int rl = ty * 4 + i;
            int r = row0 + rl;
            if (r >= M) continue;
            float v[8];
            unpack2(acc[i][0], v[0], v[1]);
            unpack2(acc[i][1], v[2], v[3]);
            unpack2(acc[i][2], v[4], v[5]);
            unpack2(acc[i][3], v[6], v[7]);
            float4 p0 = *(const float4*)&pad[rl * 64 + tx * 8];
            float4 p1 = *(const float4*)&pad[rl * 64 + tx * 8 + 4];
            v[0] += p0.x; v[1] += p0.y; v[2] += p0.z; v[3] += p0.w;
            v[4] += p1.x; v[5] += p1.y; v[6] += p1.z; v[7] += p1.w;
            int c0 = bx * 64 + tx * 8;
            size_t base = (size_t)r * DD + c0;
            if (mode == 0) {
                *(float4*)&C[base]     = make_float4(v[0], v[1], v[2], v[3]);
                *(float4*)&C[base + 4] = make_float4(v[4], v[5], v[6], v[7]);
            } else if (mode == 1) {
                *(float4*)&C[base]     = make_float4(v[0], v[1], v[2], v[3]);
                *(float4*)&C[base + 4] = make_float4(v[4], v[5], v[6], v[7]);
                float w[8];
                #pragma unroll
                for (int j = 0; j < 8; j++) {
                    w[j] = (1.0f/120.0f) * P[base + j] + (1.0f/720.0f) * P2[base + j]
                         + (1.0f/5040.0f) * P3[base + j] + (1.0f/40320.0f) * v[j];
                    if (r == c0 + j) w[j] += 1.0f/24.0f;
                }
                *(float4*)&W[base]     = make_float4(w[0], w[1], w[2], w[3]);
                *(float4*)&W[base + 4] = make_float4(w[4], w[5], w[6], w[7]);
            } else {
                float e[8];
                #pragma unroll
                for (int j = 0; j < 8; j++) {
                    e[j] = v[j] + P[base + j] + 0.5f * P2[base + j]
                         + (1.0f/6.0f) * P3[base + j];
                    if (r == c0 + j) e[j] += 1.0f;
                }
                *(float4*)&C[base]     = make_float4(e[0], e[1], e[2], e[3]);
                *(float4*)&C[base + 4] = make_float4(e[4], e[5], e[6], e[7]);
            }
        }
    }
}

__global__ void __launch_bounds__(512) k_gemm(
    const float* __restrict__ A, const float* __restrict__ B, float* __restrict__ C,
    int M, int mode, const float* __restrict__ P, const float* __restrict__ P2,
    const float* __restrict__ P3, float* __restrict__ W)
{
    gemm_tile(A, B, C, M, blockIdx.y * 128, blockIdx.x, mode, P, P2, P3, W);
}

// fused: by<8 squares (Bn = Bc@Bc, M-tile by); by>=8 doubles rows (Adst = Ar@Bc)
__global__ void __launch_bounds__(512) k_sq_dbl(
    const float* __restrict__ Bc, float* __restrict__ Bn,
    const float* __restrict__ Ar, float* __restrict__ Adst, int rows)
{
    if (blockIdx.y < 8)
        gemm_tile(Bc, Bc, Bn, DD, blockIdx.y * 128, blockIdx.x, 0, 0, 0, 0, 0);
    else
        gemm_tile(Ar, Bc, Adst, rows, (blockIdx.y - 8) * 128, blockIdx.x, 0, 0, 0, 0, 0);
}

__global__ void k_getcol(const float* __restrict__ Bc, float* __restrict__ u) {
    u[threadIdx.x] = Bc[(size_t)threadIdx.x * DD + 16];
}

// u_out = Bc @ u_in
__global__ void __launch_bounds__(256) k_matvec(
    const float* __restrict__ Bc, const float* __restrict__ u_in, float* __restrict__ u_out)
{
    __shared__ float red[256];
    int r = blockIdx.x, t = threadIdx.x;
    float s = 0.0f;
    const float* row = &Bc[(size_t)r * DD];
    for (int k = t; k < DD; k += 256)
        s = fmaf(row[k], u_in[k], s);
    red[t] = s;
    __syncthreads();
    for (int w = 128; w > 0; w >>= 1) {
        if (t < w) red[t] += red[t + w];
        __syncthreads();
    }
    if (t == 0) u_out[r] = red[0];
}

// col-16 gemv: Arows[ofs + r][16] = dot(Arows[r], u), r in [0,256)
__global__ void __launch_bounds__(256) k_gemv(const float* __restrict__ u, int ofs) {
    __shared__ float red[256];
    int r = blockIdx.x, t = threadIdx.x;
    float s = 0.0f;
    const float* row = &d_Arows[(size_t)r * DD];
    for (int k = t; k < DD; k += 256)
        s = fmaf(row[k], u[k], s);
    red[t] = s;
    __syncthreads();
    for (int w = 128; w > 0; w >>= 1) {
        if (t < w) red[t] += red[t + w];
        __syncthreads();
    }
    if (t == 0) d_Arows[(size_t)(ofs + r) * DD + 16] = red[0];
}

// ---------------- driver ----------------
extern "C" void kernel_launch(void* const* d_in, const int* in_sizes, int n_in,
                              void* d_out, int out_size) {
    const float* log_g = (const float*)d_in[0];
    int n_steps = out_size / 3;
    if (n_steps < 1) n_steps = 1;
    if (n_steps > 1024) n_steps = 1024;

    void *p0, *p1, *p2, *p3, *p4, *pA, *pua, *pub;
    cudaGetSymbolAddress(&p0, d_M0);
    cudaGetSymbolAddress(&p1, d_M1);
    cudaGetSymbolAddress(&p2, d_M2);
    cudaGetSymbolAddress(&p3, d_M3);
    cudaGetSymbolAddress(&p4, d_M4);
    cudaGetSymbolAddress(&pA, d_Arows);
    cudaGetSymbolAddress(&pua, d_ua);
    cudaGetSymbolAddress(&pub, d_ub);
    float *M0 = (float*)p0, *M1 = (float*)p1, *M2 = (float*)p2,
          *M3 = (float*)p3, *M4 = (float*)p4, *Ar = (float*)pA;
    float *ua = (float*)pua, *ub = (float*)pub;

    // Phase 0: build generator P (fp32, scale 1/(4*HBAR)) in M0
    k_build_H<<<1, 1024>>>(log_g);
    k_stageG<<<1024, 1024>>>();
    k_project<<<1024, 1024>>>();

    dim3 gfull(16, 8);
    // Phase 1: expm = order-8 Taylor (Paterson-Stockmeyer) + 2 squarings
    k_gemm<<<gfull, 512>>>(M0, M0, M1, DD, 0, 0, 0, 0, 0);      // P2 -> M1
    k_gemm<<<gfull, 512>>>(M1, M0, M2, DD, 0, 0, 0, 0, 0);      // P3 -> M2
    k_gemm<<<gfull, 512>>>(M1, M1, M4, DD, 1, M0, M1, M2, M3);  // P4 -> M4, W -> M3
    k_gemm<<<gfull, 512>>>(M4, M3, M1, DD, 2, M0, M1, M2, 0);   // E = P4@W + C1 -> M1
    k_gemm<<<gfull, 512>>>(M1, M1, M3, DD, 0, 0, 0, 0, 0);      // E^2 -> M3
    k_gemm<<<gfull, 512>>>(M3, M3, M1, DD, 0, 0, 0, 0, 0);      // U = E^4 -> M1

    // Phase 2: time doubling up to 256 rows (times 0..127), 7 fused iterations
    k_Ainit<<<2, 1024>>>();
    float* Bc = M1;   // U
    float* Bn = M3;
    int rows = 2;
    for (int kd = 0; kd < 7; kd++) {
        int dbl_tiles = (rows + 127) / 128;
        k_sq_dbl<<<dim3(16, 8 + dbl_tiles), 512>>>(
            Bc, Bn, Ar, Ar + (size_t)rows * DD, rows);
        rows <<= 1;
        float* tmp = Bc; Bc = Bn; Bn = tmp;
    }
    // Bc = U^128, rows = 256 (times 0..127 fully materialized)

    // Phase 3: tail — times 128..1023 need only column 16.
    // u_k = col16 of U^(128k);  Arows[256k + r][16] = Arows[r] . u_k
    k_getcol<<<1, 1024>>>(Bc, ua);
    float* ucur = ua;
    float* unxt = ub;
    for (int k = 1; k <= 7; k++) {
        k_gemv<<<256, 256>>>(ucur, 256 * k);
        if (k < 7) {
            k_matvec<<<DD, 256>>>(Bc, ucur, unxt);
            float* tmp = ucur; ucur = unxt; unxt = tmp;
        }
    }

    // Phase 4: extract populations
    k_extract<<<(n_steps + 255) / 256, 256>>>((float*)d_out, n_steps);
}

// round 11
// speedup vs baseline: 1.2925x; 1.2925x over previous
#include <cuda_runtime.h>
#include <math.h>

#define DD 1024
#define GBK 16

// ---------------- static device storage (no allocation allowed) ----------------
static __device__ double d_H[32 * 32];
static __device__ double d_g;
static __device__ double d_CS[DD * DD];
static __device__ double d_CA[DD * DD];
static __device__ float  d_M0[DD * DD];     // P
static __device__ float  d_M1[DD * DD];     // P2 / E / U
static __device__ float  d_M2[DD * DD];     // P3
static __device__ float  d_M3[DD * DD];     // W / ping
static __device__ float  d_M4[DD * DD];     // P4
static __device__ float  d_ua[DD];
static __device__ float  d_ub[DD];
static __device__ float  d_Arows[2048 * DD];

// ---------------- model: H on reduced 32-dim space ----------------
__device__ __forceinline__ double qmat(int r, int c) {
    if (c == r + 1) return sqrt((double)c * 0.5);
    if (r == c + 1) return sqrt((double)r * 0.5);
    return 0.0;
}

__global__ void k_build_H(const float* log_g) {
    int a = threadIdx.x;
    if (a == 0) d_g = (double)expf(log_g[0]);
    int i = a >> 5, j = a & 31;
    int si = i >> 4, vi = i & 15, v6i = vi >> 2, v10i = vi & 3;
    int sj = j >> 4, vj = j & 15, v6j = vj >> 2, v10j = vj & 3;
    const double CM2EV = 0.00012398419;
    const double E_S1 = 3.995, E_S2 = 4.9183;
    const double om6a = 596.0 * CM2EV, om10a = 919.0 * CM2EV;
    const double kap1 = -0.0964, kap2 = 0.1193;
    const double lam = 0.1825, gam = -0.018;
    double val = 0.0;
    if (si == sj) {
        if (vi == vj) val += (si == 0 ? E_S1 : E_S2) + om6a * v6i + om10a * v10i;
        if (v10i == v10j) val += (si == 0 ? kap1 : kap2) * qmat(v6i, v6j);
    } else {
        if (v6i == v6j) {
            double q2 = 0.0;
            #pragma unroll
            for (int m = 0; m < 4; m++) q2 += qmat(v10i, m) * qmat(m, v10j);
            val += lam * qmat(v10i, v10j) + gam * q2;
        }
    }
    d_H[i * 32 + j] = val;
}

// ---------------- real hermitian basis bookkeeping ----------------
__device__ __forceinline__ void decode_basis(int m, int& type, int& p, int& q) {
    if (m < 32) { type = 0; p = q = m; return; }
    int pi = (m < 528) ? (m - 32) : (m - 528);
    type = (m < 528) ? 1 : 2;
    int r = 0, cnt = 31;
    while (pi >= cnt) { pi -= cnt; r++; cnt--; }
    p = r; q = r + 1 + pi;
}

__global__ void k_stageG() {
    int n = blockIdx.x;
    int ab = threadIdx.x;
    int a = ab >> 5, b = ab & 31;
    int type, p, q;
    decode_basis(n, type, p, q);
    double v = (type == 0) ? 1.0 : 0.70710678118654752440;
    int nc = (type == 0) ? 1 : 2;
    int cc[2] = { p, q };
    int dd[2] = { q, p };
    double ww[2] = { v, (type == 2) ? -v : v };

    const double g = d_g;
    double HX = 0.0, XH = 0.0, Xab = 0.0, X16 = 0.0;
    for (int e = 0; e < nc; e++) {
        if (dd[e] == b) HX += d_H[a * 32 + cc[e]] * ww[e];
        if (cc[e] == a) XH += ww[e] * d_H[dd[e] * 32 + b];
        if (cc[e] == a && dd[e] == b) Xab += ww[e];
        if (a < 16 && b < 16 && cc[e] == a + 16 && dd[e] == b + 16) X16 += ww[e];
    }
    double diss = g * (X16 - 0.5 * Xab * (double)((a >= 16) + (b >= 16)));
    double cs, ca;
    if (type == 2) { cs = XH - HX; ca = diss; }
    else           { ca = HX - XH; cs = diss; }
    d_CS[n * DD + ab] = cs;
    d_CA[n * DD + ab] = ca;
}

// scale = (DT/HBAR) / 2^2   (s = 2 squarings for expm, order-8 Taylor)
__global__ void k_project() {
    int idx = blockIdx.x * 1024 + threadIdx.x;
    int m = idx >> 10, n = idx & 1023;
    int type, i, j;
    decode_basis(m, type, i, j);
    const double SQ2 = 1.41421356237309504880;
    double val;
    if (type == 0)      val = d_CS[n * DD + i * 33];
    else if (type == 1) val = SQ2 * d_CS[n * DD + i * 32 + j];
    else                val = SQ2 * d_CA[n * DD + i * 32 + j];
    const double scale = (1.0 / 0.6582119569) / 4.0;
    d_M0[m * DD + n] = (float)(val * scale);
}

__global__ void k_Ainit() {
    int r = blockIdx.x, c = threadIdx.x;
    float v = 0.0f;
    if (r == 0 && c < 16) v = 1.0f;
    if (r == 1 && c >= 16 && c < 32) v = 1.0f;
    d_Arows[r * DD + c] = v;
}

__global__ void k_extract(float* __restrict__ out, int n) {
    int t = blockIdx.x * blockDim.x + threadIdx.x;
    if (t >= n) return;
    out[t] = 0.0f;
    out[n + t]     = d_Arows[(size_t)(2 * t) * DD + 16];
    out[2 * n + t] = d_Arows[(size_t)(2 * t + 1) * DD + 16];
}

// ---------------- packed f32x2 helpers ----------------
__device__ __forceinline__ void ffma2(unsigned long long& acc,
                                      unsigned long long a, unsigned long long b) {
    asm("fma.rn.f32x2 %0, %1, %2, %0;" : "+l"(acc) : "l"(a), "l"(b));
}
__device__ __forceinline__ unsigned long long pack2(float x) {
    unsigned long long r; unsigned u = __float_as_uint(x);
    asm("mov.b64 %0, {%1, %1};" : "=l"(r) : "r"(u));
    return r;
}
__device__ __forceinline__ void unpack2(unsigned long long v, float& lo, float& hi) {
    unsigned a, b;
    asm("mov.b64 {%0, %1}, %2;" : "=r"(a), "=r"(b) : "l"(v));
    lo = __uint_as_float(a); hi = __uint_as_float(b);
}

// ---------------- GEMM: C(MxDD)=A@B; 64x64 tile; 512 thr = 2 K-teams of 256 ----------------
// Warp-shape-aware mapping: within a team, tx = (wid&1)*8 + (lane&7), ty = (wid>>1)*4 + (lane>>3)
// -> per warp-kk: sA = 4 distinct 16B (1 broadcast wavefront), sB = 8 distinct 16B (1 wavefront).
// Team 0 sums k in [0,512), team 1 in [512,1024); deterministic lo+hi combine via pad.
// mode 0: C = v
// mode 1: C(=P4) = v;  W = I/24 + P/120 + P2/720 + P3/5040 + v/40320
// mode 2: C(=E)  = v + I + P + P2/2 + P3/6
__device__ __forceinline__ void gemm_tile512(
    const float* __restrict__ A, const float* __restrict__ B, float* __restrict__ C,
    int M, int row0, int bx, int mode,
    const float* __restrict__ P, const float* __restrict__ P2,
    const float* __restrict__ P3, float* __restrict__ W)
{
    __shared__ float smem[2][2][GBK][64];     // [team][A|B][k][64] = 16KB
    float* pad = &smem[0][0][0][0];           // aliased 64x64 partial pad (used after final sync)
    int tid = threadIdx.x;
    int team = tid >> 8;
    int t = tid & 255;
    // z-ordered micro-tile mapping (bijective on t):
    int tx = ((t >> 5) & 1) * 8 + (t & 7);    // 16 col-groups; 8 distinct per warp
    int ty = (t >> 6) * 4 + ((t >> 3) & 3);   // 16 row-groups; 4 distinct per warp
    int k0 = team << 9;
    float (*sA)[64] = smem[team][0];
    float (*sB)[64] = smem[team][1];

    unsigned long long acc[4][2];
    #pragma unroll
    for (int i = 0; i < 4; i++) { acc[i][0] = 0ULL; acc[i][1] = 0ULL; }

    for (int kt = 0; kt < 512; kt += GBK) {
        {   // stage A tile (transposed)
            int r = t >> 2, kc = t & 3;
            float4 v = make_float4(0.f, 0.f, 0.f, 0.f);
            if (row0 + r < M)
                v = *(const float4*)&A[(size_t)(row0 + r) * DD + k0 + kt + kc * 4];
            sA[kc * 4 + 0][r] = v.x;
            sA[kc * 4 + 1][r] = v.y;
            sA[kc * 4 + 2][r] = v.z;
            sA[kc * 4 + 3][r] = v.w;
        }
        {   // stage B tile
            int k = t >> 4, nc = t & 15;
            *(float4*)&sB[k][nc * 4] =
                *(const float4*)&B[(size_t)(k0 + kt + k) * DD + bx * 64 + nc * 4];
        }
        __syncthreads();
        #pragma unroll
        for (int kk = 0; kk < GBK; kk++) {
            float4 av = *(const float4*)&sA[kk][ty * 4];
            ulonglong2 bv = *(const ulonglong2*)&sB[kk][tx * 4];
            unsigned long long a0 = pack2(av.x), a1 = pack2(av.y),
                               a2 = pack2(av.z), a3 = pack2(av.w);
            ffma2(acc[0][0], a0, bv.x); ffma2(acc[0][1], a0, bv.y);
            ffma2(acc[1][0], a1, bv.x); ffma2(acc[1][1], a1, bv.y);
            ffma2(acc[2][0], a2, bv.x); ffma2(acc[2][1], a2, bv.y);
            ffma2(acc[3][0], a3, bv.x); ffma2(acc[3][1], a3, bv.y);
        }
        __syncthreads();
    }

    // combine: team 1 deposits its partials, team 0 adds (lo-half + hi-half, deterministic)
    if (team == 1) {
        #pragma unroll
        for (int i = 0; i < 4; i++) {
            float v[4];
            unpack2(acc[i][0], v[0], v[1]);
            unpack2(acc[i][1], v[2], v[3]);
            *(float4*)&pad[(ty * 4 + i) * 64 + tx * 4] = make_float4(v[0], v[1], v[2], v[3]);
        }
    }
    __syncthreads();
    if (team == 0) {
        #pragma unroll
        for (int i = 0; i < 4; i++) {
            int r = row0 + ty * 4 + i;
            if (r >= M) continue;
            float v[4];
            unpack2(acc[i][0], v[0], v[1]);
            unpack2(acc[i][1], v[2], v[3]);
            float4 pv = *(const float4*)&pad[(ty * 4 + i) * 64 + tx * 4];
            v[0] += pv.x; v[1] += pv.y; v[2] += pv.z; v[3] += pv.w;
            int c0 = bx * 64 + tx * 4;
            size_t base = (size_t)r * DD + c0;
            if (mode == 0) {
                *(float4*)&C[base] = make_float4(v[0], v[1], v[2], v[3]);
            } else if (mode == 1) {
                *(float4*)&C[base] = make_float4(v[0], v[1], v[2], v[3]);
                float w[4];
                #pragma unroll
                for (int j = 0; j < 4; j++) {
                    w[j] = (1.0f/120.0f) * P[base + j] + (1.0f/720.0f) * P2[base + j]
                         + (1.0f/5040.0f) * P3[base + j] + (1.0f/40320.0f) * v[j];
                    if (r == c0 + j) w[j] += 1.0f/24.0f;
                }
                *(float4*)&W[base] = make_float4(w[0], w[1], w[2], w[3]);
            } else {
                float e[4];
                #pragma unroll
                for (int j = 0; j < 4; j++) {
                    e[j] = v[j] + P[base + j] + 0.5f * P2[base + j]
                         + (1.0f/6.0f) * P3[base + j];
                    if (r == c0 + j) e[j] += 1.0f;
                }
                *(float4*)&C[base] = make_float4(e[0], e[1], e[2], e[3]);
            }
        }
    }
}

__global__ void __launch_bounds__(512, 2) k_gemm512(
    const float* __restrict__ A, const float* __restrict__ B, float* __restrict__ C,
    int M, int mode, const float* __restrict__ P, const float* __restrict__ P2,
    const float* __restrict__ P3, float* __restrict__ W)
{
    gemm_tile512(A, B, C, M, blockIdx.y * 64, blockIdx.x, mode, P, P2, P3, W);
}

// fused: by<16 squares (Bn = Bc@Bc); by>=16 doubles rows (Adst = Ar@Bc)
__global__ void __launch_bounds__(512, 2) k_sq_dbl512(
    const float* __restrict__ Bc, float* __restrict__ Bn,
    const float* __restrict__ Ar, float* __restrict__ Adst, int rows)
{
    if (blockIdx.y < 16)
        gemm_tile512(Bc, Bc, Bn, DD, blockIdx.y * 64, blockIdx.x, 0, 0, 0, 0, 0);
    else
        gemm_tile512(Ar, Bc, Adst, rows, (blockIdx.y - 16) * 64, blockIdx.x, 0, 0, 0, 0, 0);
}

__global__ void k_getcol(const float* __restrict__ Bc, float* __restrict__ u) {
    u[threadIdx.x] = Bc[(size_t)threadIdx.x * DD + 16];
}

// u_out = Bc @ u_in
__global__ void __launch_bounds__(256) k_matvec(
    const float* __restrict__ Bc, const float* __restrict__ u_in, float* __restrict__ u_out)
{
    __shared__ float red[256];
    int r = blockIdx.x, t = threadIdx.x;
    float s = 0.0f;
    const float* row = &Bc[(size_t)r * DD];
    for (int k = t; k < DD; k += 256)
        s = fmaf(row[k], u_in[k], s);
    red[t] = s;
    __syncthreads();
    for (int w = 128; w > 0; w >>= 1) {
        if (t < w) red[t] += red[t + w];
        __syncthreads();
    }
    if (t == 0) u_out[r] = red[0];
}

// col-16 gemv: Arows[ofs + r][16] = dot(Arows[r], u), r in [0,256)
__global__ void __launch_bounds__(256) k_gemv(const float* __restrict__ u, int ofs) {
    __shared__ float red[256];
    int r = blockIdx.x, t = threadIdx.x;
    float s = 0.0f;
    const float* row = &d_Arows[(size_t)r * DD];
    for (int k = t; k < DD; k += 256)
        s = fmaf(row[k], u[k], s);
    red[t] = s;
    __syncthreads();
    for (int w = 128; w > 0; w >>= 1) {
        if (t < w) red[t] += red[t + w];
        __syncthreads();
    }
    if (t == 0) d_Arows[(size_t)(ofs + r) * DD + 16] = red[0];
}

// ---------------- driver ----------------
extern "C" void kernel_launch(void* const* d_in, const int* in_sizes, int n_in,
                              void* d_out, int out_size) {
    const float* log_g = (const float*)d_in[0];
    int n_steps = out_size / 3;
    if (n_steps < 1) n_steps = 1;
    if (n_steps > 1024) n_steps = 1024;

    void *p0, *p1, *p2, *p3, *p4, *pA, *pua, *pub;
    cudaGetSymbolAddress(&p0, d_M0);
    cudaGetSymbolAddress(&p1, d_M1);
    cudaGetSymbolAddress(&p2, d_M2);
    cudaGetSymbolAddress(&p3, d_M3);
    cudaGetSymbolAddress(&p4, d_M4);
    cudaGetSymbolAddress(&pA, d_Arows);
    cudaGetSymbolAddress(&pua, d_ua);
    cudaGetSymbolAddress(&pub, d_ub);
    float *M0 = (float*)p0, *M1 = (float*)p1, *M2 = (float*)p2,
          *M3 = (float*)p3, *M4 = (float*)p4, *Ar = (float*)pA;
    float *ua = (float*)pua, *ub = (float*)pub;

    // Phase 0: build generator P (fp32, scale 1/(4*HBAR)) in M0
    k_build_H<<<1, 1024>>>(log_g);
    k_stageG<<<1024, 1024>>>();
    k_project<<<1024, 1024>>>();

    dim3 gfull(16, 16);
    // Phase 1: expm = order-8 Taylor (Paterson-Stockmeyer) + 2 squarings
    k_gemm512<<<gfull, 512>>>(M0, M0, M1, DD, 0, 0, 0, 0, 0);       // P2 -> M1
    k_gemm512<<<gfull, 512>>>(M1, M0, M2, DD, 0, 0, 0, 0, 0);       // P3 -> M2
    k_gemm512<<<gfull, 512>>>(M1, M1, M4, DD, 1, M0, M1, M2, M3);   // P4 -> M4, W -> M3
    k_gemm512<<<gfull, 512>>>(M4, M3, M1, DD, 2, M0, M1, M2, 0);    // E = P4@W + C1 -> M1
    k_gemm512<<<gfull, 512>>>(M1, M1, M3, DD, 0, 0, 0, 0, 0);       // E^2 -> M3
    k_gemm512<<<gfull, 512>>>(M3, M3, M1, DD, 0, 0, 0, 0, 0);       // U = E^4 -> M1

    // Phase 2: time doubling up to 256 rows (times 0..127), 7 fused iterations
    k_Ainit<<<2, 1024>>>();
    float* Bc = M1;   // U
    float* Bn = M3;
    int rows = 2;
    for (int kd = 0; kd < 7; kd++) {
        int dbl_tiles = (rows + 63) / 64;
        k_sq_dbl512<<<dim3(16, 16 + dbl_tiles), 512>>>(
            Bc, Bn, Ar, Ar + (size_t)rows * DD, rows);
        rows <<= 1;
        float* tmp = Bc; Bc = Bn; Bn = tmp;
    }
    // Bc = U^128, rows = 256 (times 0..127 fully materialized)

    // Phase 3: tail — times 128..1023 need only column 16.
    // u_k = col16 of U^(128k);  Arows[256k + r][16] = Arows[r] . u_k
    k_getcol<<<1, 1024>>>(Bc, ua);
    float* ucur = ua;
    float* unxt = ub;
    for (int k = 1; k <= 7; k++) {
        k_gemv<<<256, 256>>>(ucur, 256 * k);
        if (k < 7) {
            k_matvec<<<DD, 256>>>(Bc, ucur, unxt);
            float* tmp = ucur; ucur = unxt; unxt = tmp;
        }
    }

    // Phase 4: extract populations
    k_extract<<<(n_steps + 255) / 256, 256>>>((float*)d_out, n_steps);
}

// round 12
// speedup vs baseline: 1.3024x; 1.0076x over previous
#include <cuda_runtime.h>
#include <math.h>

#define DD 1024
#define GBK 16

// ---------------- static device storage (no allocation allowed) ----------------
static __device__ double d_H[32 * 32];
static __device__ double d_g;
static __device__ double d_CS[DD * DD];
static __device__ double d_CA[DD * DD];
static __device__ float  d_M0[DD * DD];     // P
static __device__ float  d_M1[DD * DD];     // P2 / E / U
static __device__ float  d_M2[DD * DD];     // P3
static __device__ float  d_M3[DD * DD];     // W / ping
static __device__ float  d_M4[DD * DD];     // P4
static __device__ float  d_ua[DD];
static __device__ float  d_ub[DD];
static __device__ float  d_Arows[2048 * DD];

// ---------------- model: H on reduced 32-dim space ----------------
__device__ __forceinline__ double qmat(int r, int c) {
    if (c == r + 1) return sqrt((double)c * 0.5);
    if (r == c + 1) return sqrt((double)r * 0.5);
    return 0.0;
}

__global__ void k_build_H(const float* log_g) {
    int a = threadIdx.x;
    if (a == 0) d_g = (double)expf(log_g[0]);
    int i = a >> 5, j = a & 31;
    int si = i >> 4, vi = i & 15, v6i = vi >> 2, v10i = vi & 3;
    int sj = j >> 4, vj = j & 15, v6j = vj >> 2, v10j = vj & 3;
    const double CM2EV = 0.00012398419;
    const double E_S1 = 3.995, E_S2 = 4.9183;
    const double om6a = 596.0 * CM2EV, om10a = 919.0 * CM2EV;
    const double kap1 = -0.0964, kap2 = 0.1193;
    const double lam = 0.1825, gam = -0.018;
    double val = 0.0;
    if (si == sj) {
        if (vi == vj) val += (si == 0 ? E_S1 : E_S2) + om6a * v6i + om10a * v10i;
        if (v10i == v10j) val += (si == 0 ? kap1 : kap2) * qmat(v6i, v6j);
    } else {
        if (v6i == v6j) {
            double q2 = 0.0;
            #pragma unroll
            for (int m = 0; m < 4; m++) q2 += qmat(v10i, m) * qmat(m, v10j);
            val += lam * qmat(v10i, v10j) + gam * q2;
        }
    }
    d_H[i * 32 + j] = val;
}

// ---------------- real hermitian basis bookkeeping ----------------
__device__ __forceinline__ void decode_basis(int m, int& type, int& p, int& q) {
    if (m < 32) { type = 0; p = q = m; return; }
    int pi = (m < 528) ? (m - 32) : (m - 528);
    type = (m < 528) ? 1 : 2;
    int r = 0, cnt = 31;
    while (pi >= cnt) { pi -= cnt; r++; cnt--; }
    p = r; q = r + 1 + pi;
}

__global__ void k_stageG() {
    int n = blockIdx.x;
    int ab = threadIdx.x;
    int a = ab >> 5, b = ab & 31;
    int type, p, q;
    decode_basis(n, type, p, q);
    double v = (type == 0) ? 1.0 : 0.70710678118654752440;
    int nc = (type == 0) ? 1 : 2;
    int cc[2] = { p, q };
    int dd[2] = { q, p };
    double ww[2] = { v, (type == 2) ? -v : v };

    const double g = d_g;
    double HX = 0.0, XH = 0.0, Xab = 0.0, X16 = 0.0;
    for (int e = 0; e < nc; e++) {
        if (dd[e] == b) HX += d_H[a * 32 + cc[e]] * ww[e];
        if (cc[e] == a) XH += ww[e] * d_H[dd[e] * 32 + b];
        if (cc[e] == a && dd[e] == b) Xab += ww[e];
        if (a < 16 && b < 16 && cc[e] == a + 16 && dd[e] == b + 16) X16 += ww[e];
    }
    double diss = g * (X16 - 0.5 * Xab * (double)((a >= 16) + (b >= 16)));
    double cs, ca;
    if (type == 2) { cs = XH - HX; ca = diss; }
    else           { ca = HX - XH; cs = diss; }
    d_CS[n * DD + ab] = cs;
    d_CA[n * DD + ab] = ca;
}

// scale = (DT/HBAR) / 2^2   (s = 2 squarings for expm, order-8 Taylor)
__global__ void k_project() {
    int idx = blockIdx.x * 1024 + threadIdx.x;
    int m = idx >> 10, n = idx & 1023;
    int type, i, j;
    decode_basis(m, type, i, j);
    const double SQ2 = 1.41421356237309504880;
    double val;
    if (type == 0)      val = d_CS[n * DD + i * 33];
    else if (type == 1) val = SQ2 * d_CS[n * DD + i * 32 + j];
    else                val = SQ2 * d_CA[n * DD + i * 32 + j];
    const double scale = (1.0 / 0.6582119569) / 4.0;
    d_M0[m * DD + n] = (float)(val * scale);
}

__global__ void k_Ainit() {
    int r = blockIdx.x, c = threadIdx.x;
    float v = 0.0f;
    if (r == 0 && c < 16) v = 1.0f;
    if (r == 1 && c >= 16 && c < 32) v = 1.0f;
    d_Arows[r * DD + c] = v;
}

__global__ void k_extract(float* __restrict__ out, int n) {
    int t = blockIdx.x * blockDim.x + threadIdx.x;
    if (t >= n) return;
    out[t] = 0.0f;
    out[n + t]     = d_Arows[(size_t)(2 * t) * DD + 16];
    out[2 * n + t] = d_Arows[(size_t)(2 * t + 1) * DD + 16];
}

// ---------------- packed f32x2 helpers ----------------
__device__ __forceinline__ void ffma2(unsigned long long& acc,
                                      unsigned long long a, unsigned long long b) {
    asm("fma.rn.f32x2 %0, %1, %2, %0;" : "+l"(acc) : "l"(a), "l"(b));
}
__device__ __forceinline__ unsigned long long pack2(float x) {
    unsigned long long r; unsigned u = __float_as_uint(x);
    asm("mov.b64 %0, {%1, %1};" : "=l"(r) : "r"(u));
    return r;
}
__device__ __forceinline__ void unpack2(unsigned long long v, float& lo, float& hi) {
    unsigned a, b;
    asm("mov.b64 {%0, %1}, %2;" : "=r"(a), "=r"(b) : "l"(v));
    lo = __uint_as_float(a); hi = __uint_as_float(b);
}

// ---------------- GEMM: C(MxDD)=A@B; 64x64 tile; 512 thr = 2 K-teams of 256 ----------------
// Double-buffered staging: one __syncthreads per kt-iteration; iteration stages
// the NEXT k-slab into the alternate buffer before computing the current one.
// Warp mapping: tx = ((t>>5)&1)*8 + (t&7), ty = (t>>6)*4 + ((t>>3)&3)
// -> per warp-kk: sA 1 broadcast wavefront, sB 1 wavefront.
// Team 0 sums k in [0,512), team 1 in [512,1024); deterministic lo+hi combine via pad.
// mode 0: C = v
// mode 1: C(=P4) = v;  W = I/24 + P/120 + P2/720 + P3/5040 + v/40320
// mode 2: C(=E)  = v + I + P + P2/2 + P3/6
__device__ __forceinline__ void gemm_tile512(
    const float* __restrict__ A, const float* __restrict__ B, float* __restrict__ C,
    int M, int row0, int bx, int mode,
    const float* __restrict__ P, const float* __restrict__ P2,
    const float* __restrict__ P3, float* __restrict__ W)
{
    __shared__ float smem[2][2][2][GBK][64];  // [buf][team][A|B][k][64] = 32KB
    float* pad = &smem[0][0][0][0][0];        // 64x64 combine pad (aliases buf 0; used after final sync)
    int tid = threadIdx.x;
    int team = tid >> 8;
    int t = tid & 255;
    int tx = ((t >> 5) & 1) * 8 + (t & 7);
    int ty = (t >> 6) * 4 + ((t >> 3) & 3);
    int k0 = team << 9;
    int ar = t >> 2, akc = t & 3;             // A staging coords
    int bk = t >> 4, bnc = t & 15;            // B staging coords
    bool arow_ok = (row0 + ar < M);
    const float* Abase = &A[(size_t)(row0 + (arow_ok ? ar : 0)) * DD + k0 + akc * 4];
    const float* Bbase = &B[(size_t)(k0 + bk) * DD + bx * 64 + bnc * 4];

    unsigned long long acc[4][2];
    #pragma unroll
    for (int i = 0; i < 4; i++) { acc[i][0] = 0ULL; acc[i][1] = 0ULL; }

    {   // prologue: stage slab 0 into buf 0
        float4 va = make_float4(0.f, 0.f, 0.f, 0.f);
        if (arow_ok) va = *(const float4*)Abase;
        float (*dA)[64] = smem[0][team][0];
        dA[akc * 4 + 0][ar] = va.x;
        dA[akc * 4 + 1][ar] = va.y;
        dA[akc * 4 + 2][ar] = va.z;
        dA[akc * 4 + 3][ar] = va.w;
        *(float4*)&smem[0][team][1][bk][bnc * 4] = *(const float4*)Bbase;
    }
    __syncthreads();

    for (int it = 0; it < 32; it++) {
        int cur = it & 1;
        if (it < 31) {   // stage next slab into alternate buffer (overlaps other warps' compute)
            int kt = (it + 1) * GBK;
            float4 va = make_float4(0.f, 0.f, 0.f, 0.f);
            if (arow_ok) va = *(const float4*)(Abase + kt);
            float4 vb = *(const float4*)(Bbase + (size_t)kt * DD);
            float (*dA)[64] = smem[cur ^ 1][team][0];
            dA[akc * 4 + 0][ar] = va.x;
            dA[akc * 4 + 1][ar] = va.y;
            dA[akc * 4 + 2][ar] = va.z;
            dA[akc * 4 + 3][ar] = va.w;
            *(float4*)&smem[cur ^ 1][team][1][bk][bnc * 4] = vb;
        }
        float (*sA)[64] = smem[cur][team][0];
        float (*sB)[64] = smem[cur][team][1];
        #pragma unroll
        for (int kk = 0; kk < GBK; kk++) {
            float4 av = *(const float4*)&sA[kk][ty * 4];
            ulonglong2 bv = *(const ulonglong2*)&sB[kk][tx * 4];
            unsigned long long a0 = pack2(av.x), a1 = pack2(av.y),
                               a2 = pack2(av.z), a3 = pack2(av.w);
            ffma2(acc[0][0], a0, bv.x); ffma2(acc[0][1], a0, bv.y);
            ffma2(acc[1][0], a1, bv.x); ffma2(acc[1][1], a1, bv.y);
            ffma2(acc[2][0], a2, bv.x); ffma2(acc[2][1], a2, bv.y);
            ffma2(acc[3][0], a3, bv.x); ffma2(acc[3][1], a3, bv.y);
        }
        __syncthreads();
    }

    // combine: team 1 deposits its partials, team 0 adds (lo-half + hi-half, deterministic)
    if (team == 1) {
        #pragma unroll
        for (int i = 0; i < 4; i++) {
            float v[4];
            unpack2(acc[i][0], v[0], v[1]);
            unpack2(acc[i][1], v[2], v[3]);
            *(float4*)&pad[(ty * 4 + i) * 64 + tx * 4] = make_float4(v[0], v[1], v[2], v[3]);
        }
    }
    __syncthreads();
    if (team == 0) {
        #pragma unroll
        for (int i = 0; i < 4; i++) {
            int r = row0 + ty * 4 + i;
            if (r >= M) continue;
            float v[4];
            unpack2(acc[i][0], v[0], v[1]);
            unpack2(acc[i][1], v[2], v[3]);
            float4 pv = *(const float4*)&pad[(ty * 4 + i) * 64 + tx * 4];
            v[0] += pv.x; v[1] += pv.y; v[2] += pv.z; v[3] += pv.w;
            int c0 = bx * 64 + tx * 4;
            size_t base = (size_t)r * DD + c0;
            if (mode == 0) {
                *(float4*)&C[base] = make_float4(v[0], v[1], v[2], v[3]);
            } else if (mode == 1) {
                *(float4*)&C[base] = make_float4(v[0], v[1], v[2], v[3]);
                float w[4];
                #pragma unroll
                for (int j = 0; j < 4; j++) {
                    w[j] = (1.0f/120.0f) * P[base + j] + (1.0f/720.0f) * P2[base + j]
                         + (1.0f/5040.0f) * P3[base + j] + (1.0f/40320.0f) * v[j];
                    if (r == c0 + j) w[j] += 1.0f/24.0f;
                }
                *(float4*)&W[base] = make_float4(w[0], w[1], w[2], w[3]);
            } else {
                float e[4];
                #pragma unroll
                for (int j = 0; j < 4; j++) {
                    e[j] = v[j] + P[base + j] + 0.5f * P2[base + j]
                         + (1.0f/6.0f) * P3[base + j];
                    if (r == c0 + j) e[j] += 1.0f;
                }
                *(float4*)&C[base] = make_float4(e[0], e[1], e[2], e[3]);
            }
        }
    }
}

__global__ void __launch_bounds__(512, 2) k_gemm512(
    const float* __restrict__ A, const float* __restrict__ B, float* __restrict__ C,
    int M, int mode, const float* __restrict__ P, const float* __restrict__ P2,
    const float* __restrict__ P3, float* __restrict__ W)
{
    gemm_tile512(A, B, C, M, blockIdx.y * 64, blockIdx.x, mode, P, P2, P3, W);
}

// fused: by<16 squares (Bn = Bc@Bc); by>=16 doubles rows (Adst = Ar@Bc)
__global__ void __launch_bounds__(512, 2) k_sq_dbl512(
    const float* __restrict__ Bc, float* __restrict__ Bn,
    const float* __restrict__ Ar, float* __restrict__ Adst, int rows)
{
    if (blockIdx.y < 16)
        gemm_tile512(Bc, Bc, Bn, DD, blockIdx.y * 64, blockIdx.x, 0, 0, 0, 0, 0);
    else
        gemm_tile512(Ar, Bc, Adst, rows, (blockIdx.y - 16) * 64, blockIdx.x, 0, 0, 0, 0, 0);
}

__global__ void k_getcol(const float* __restrict__ Bc, float* __restrict__ u) {
    u[threadIdx.x] = Bc[(size_t)threadIdx.x * DD + 16];
}

// fused tail step: blocks [0,256) do col-16 gemv (Arows[ofs+b][16] = Arows[b].u);
// blocks [256,1280) do matvec row (u_out[b-256] = Bc[b-256].u). Both only READ u.
__global__ void __launch_bounds__(256) k_tail(
    const float* __restrict__ Bc, const float* __restrict__ u,
    float* __restrict__ u_out, int ofs)
{
    __shared__ float red[256];
    int b = blockIdx.x, t = threadIdx.x;
    const float* row = (b < 256) ? &d_Arows[(size_t)b * DD]
                                 : &Bc[(size_t)(b - 256) * DD];
    float s = 0.0f;
    for (int k = t; k < DD; k += 256)
        s = fmaf(row[k], u[k], s);
    red[t] = s;
    __syncthreads();
    for (int w = 128; w > 0; w >>= 1) {
        if (t < w) red[t] += red[t + w];
        __syncthreads();
    }
    if (t == 0) {
        if (b < 256) d_Arows[(size_t)(ofs + b) * DD + 16] = red[0];
        else         u_out[b - 256] = red[0];
    }
}

// ---------------- driver ----------------
extern "C" void kernel_launch(void* const* d_in, const int* in_sizes, int n_in,
                              void* d_out, int out_size) {
    const float* log_g = (const float*)d_in[0];
    int n_steps = out_size / 3;
    if (n_steps < 1) n_steps = 1;
    if (n_steps > 1024) n_steps = 1024;

    void *p0, *p1, *p2, *p3, *p4, *pA, *pua, *pub;
    cudaGetSymbolAddress(&p0, d_M0);
    cudaGetSymbolAddress(&p1, d_M1);
    cudaGetSymbolAddress(&p2, d_M2);
    cudaGetSymbolAddress(&p3, d_M3);
    cudaGetSymbolAddress(&p4, d_M4);
    cudaGetSymbolAddress(&pA, d_Arows);
    cudaGetSymbolAddress(&pua, d_ua);
    cudaGetSymbolAddress(&pub, d_ub);
    float *M0 = (float*)p0, *M1 = (float*)p1, *M2 = (float*)p2,
          *M3 = (float*)p3, *M4 = (float*)p4, *Ar = (float*)pA;
    float *ua = (float*)pua, *ub = (float*)pub;

    // Phase 0: build generator P (fp32, scale 1/(4*HBAR)) in M0
    k_build_H<<<1, 1024>>>(log_g);
    k_stageG<<<1024, 1024>>>();
    k_project<<<1024, 1024>>>();

    dim3 gfull(16, 16);
    // Phase 1: expm = order-8 Taylor (Paterson-Stockmeyer) + 2 squarings
    k_gemm512<<<gfull, 512>>>(M0, M0, M1, DD, 0, 0, 0, 0, 0);       // P2 -> M1
    k_gemm512<<<gfull, 512>>>(M1, M0, M2, DD, 0, 0, 0, 0, 0);       // P3 -> M2
    k_gemm512<<<gfull, 512>>>(M1, M1, M4, DD, 1, M0, M1, M2, M3);   // P4 -> M4, W -> M3
    k_gemm512<<<gfull, 512>>>(M4, M3, M1, DD, 2, M0, M1, M2, 0);    // E = P4@W + C1 -> M1
    k_gemm512<<<gfull, 512>>>(M1, M1, M3, DD, 0, 0, 0, 0, 0);       // E^2 -> M3
    k_gemm512<<<gfull, 512>>>(M3, M3, M1, DD, 0, 0, 0, 0, 0);       // U = E^4 -> M1

    // Phase 2: time doubling up to 256 rows (times 0..127), 7 fused iterations
    k_Ainit<<<2, 1024>>>();
    float* Bc = M1;   // U
    float* Bn = M3;
    int rows = 2;
    for (int kd = 0; kd < 7; kd++) {
        int dbl_tiles = (rows + 63) / 64;
        k_sq_dbl512<<<dim3(16, 16 + dbl_tiles), 512>>>(
            Bc, Bn, Ar, Ar + (size_t)rows * DD, rows);
        rows <<= 1;
        float* tmp = Bc; Bc = Bn; Bn = tmp;
    }
    // Bc = U^128, rows = 256 (times 0..127 fully materialized)

    // Phase 3: tail — times 128..1023 need only column 16.
    // u_k = col16 of U^(128k);  Arows[256k + b][16] = Arows[b] . u_k
    k_getcol<<<1, 1024>>>(Bc, ua);
    float* ucur = ua;
    float* unxt = ub;
    for (int k = 1; k <= 7; k++) {
        int nblocks = (k < 7) ? 1280 : 256;   // fuse gemv + matvec while matvec still needed
        k_tail<<<nblocks, 256>>>(Bc, ucur, unxt, 256 * k);
        float* tmp = ucur; ucur = unxt; unxt = tmp;
    }

    // Phase 4: extract populations
    k_extract<<<(n_steps + 255) / 256, 256>>>((float*)d_out, n_steps);
}

// round 13
// speedup vs baseline: 1.3026x; 1.0002x over previous
#include <cuda_runtime.h>
#include <math.h>

#define DD 1024
#define GBK 16

// ---------------- static device storage (no allocation allowed) ----------------
static __device__ double d_H[32 * 32];
static __device__ double d_g;
static __device__ double d_CS[DD * DD];
static __device__ double d_CA[DD * DD];
static __device__ float  d_M0[DD * DD];     // P
static __device__ float  d_M1[DD * DD];     // P2 / E / U
static __device__ float  d_M2[DD * DD];     // P3
static __device__ float  d_M3[DD * DD];     // W / ping
static __device__ float  d_M4[DD * DD];     // P4
static __device__ float  d_ua[DD];
static __device__ float  d_ub[DD];
static __device__ float  d_Arows[2048 * DD];

// ---------------- model: H on reduced 32-dim space ----------------
__device__ __forceinline__ double qmat(int r, int c) {
    if (c == r + 1) return sqrt((double)c * 0.5);
    if (r == c + 1) return sqrt((double)r * 0.5);
    return 0.0;
}

__global__ void k_build_H(const float* log_g) {
    int a = threadIdx.x;
    if (a == 0) d_g = (double)expf(log_g[0]);
    int i = a >> 5, j = a & 31;
    int si = i >> 4, vi = i & 15, v6i = vi >> 2, v10i = vi & 3;
    int sj = j >> 4, vj = j & 15, v6j = vj >> 2, v10j = vj & 3;
    const double CM2EV = 0.00012398419;
    const double E_S1 = 3.995, E_S2 = 4.9183;
    const double om6a = 596.0 * CM2EV, om10a = 919.0 * CM2EV;
    const double kap1 = -0.0964, kap2 = 0.1193;
    const double lam = 0.1825, gam = -0.018;
    double val = 0.0;
    if (si == sj) {
        if (vi == vj) val += (si == 0 ? E_S1 : E_S2) + om6a * v6i + om10a * v10i;
        if (v10i == v10j) val += (si == 0 ? kap1 : kap2) * qmat(v6i, v6j);
    } else {
        if (v6i == v6j) {
            double q2 = 0.0;
            #pragma unroll
            for (int m = 0; m < 4; m++) q2 += qmat(v10i, m) * qmat(m, v10j);
            val += lam * qmat(v10i, v10j) + gam * q2;
        }
    }
    d_H[i * 32 + j] = val;
}

// ---------------- real hermitian basis bookkeeping ----------------
__device__ __forceinline__ void decode_basis(int m, int& type, int& p, int& q) {
    if (m < 32) { type = 0; p = q = m; return; }
    int pi = (m < 528) ? (m - 32) : (m - 528);
    type = (m < 528) ? 1 : 2;
    int r = 0, cnt = 31;
    while (pi >= cnt) { pi -= cnt; r++; cnt--; }
    p = r; q = r + 1 + pi;
}

__global__ void k_stageG() {
    int n = blockIdx.x;
    int ab = threadIdx.x;
    int a = ab >> 5, b = ab & 31;
    int type, p, q;
    decode_basis(n, type, p, q);
    double v = (type == 0) ? 1.0 : 0.70710678118654752440;
    int nc = (type == 0) ? 1 : 2;
    int cc[2] = { p, q };
    int dd[2] = { q, p };
    double ww[2] = { v, (type == 2) ? -v : v };

    const double g = d_g;
    double HX = 0.0, XH = 0.0, Xab = 0.0, X16 = 0.0;
    for (int e = 0; e < nc; e++) {
        if (dd[e] == b) HX += d_H[a * 32 + cc[e]] * ww[e];
        if (cc[e] == a) XH += ww[e] * d_H[dd[e] * 32 + b];
        if (cc[e] == a && dd[e] == b) Xab += ww[e];
        if (a < 16 && b < 16 && cc[e] == a + 16 && dd[e] == b + 16) X16 += ww[e];
    }
    double diss = g * (X16 - 0.5 * Xab * (double)((a >= 16) + (b >= 16)));
    double cs, ca;
    if (type == 2) { cs = XH - HX; ca = diss; }
    else           { ca = HX - XH; cs = diss; }
    d_CS[n * DD + ab] = cs;
    d_CA[n * DD + ab] = ca;
}

// scale = (DT/HBAR) / 2^2   (s = 2 squarings for expm, order-8 Taylor)
__global__ void k_project() {
    int idx = blockIdx.x * 1024 + threadIdx.x;
    int m = idx >> 10, n = idx & 1023;
    int type, i, j;
    decode_basis(m, type, i, j);
    const double SQ2 = 1.41421356237309504880;
    double val;
    if (type == 0)      val = d_CS[n * DD + i * 33];
    else if (type == 1) val = SQ2 * d_CS[n * DD + i * 32 + j];
    else                val = SQ2 * d_CA[n * DD + i * 32 + j];
    const double scale = (1.0 / 0.6582119569) / 4.0;
    d_M0[m * DD + n] = (float)(val * scale);
}

__global__ void k_Ainit() {
    int r = blockIdx.x, c = threadIdx.x;
    float v = 0.0f;
    if (r == 0 && c < 16) v = 1.0f;
    if (r == 1 && c >= 16 && c < 32) v = 1.0f;
    d_Arows[r * DD + c] = v;
}

__global__ void k_extract(float* __restrict__ out, int n) {
    int t = blockIdx.x * blockDim.x + threadIdx.x;
    if (t >= n) return;
    out[t] = 0.0f;
    out[n + t]     = d_Arows[(size_t)(2 * t) * DD + 16];
    out[2 * n + t] = d_Arows[(size_t)(2 * t + 1) * DD + 16];
}

// ---------------- packed f32x2 helpers ----------------
__device__ __forceinline__ void ffma2(unsigned long long& acc,
                                      unsigned long long a, unsigned long long b) {
    asm("fma.rn.f32x2 %0, %1, %2, %0;" : "+l"(acc) : "l"(a), "l"(b));
}
__device__ __forceinline__ unsigned long long pack2(float x) {
    unsigned long long r; unsigned u = __float_as_uint(x);
    asm("mov.b64 %0, {%1, %1};" : "=l"(r) : "r"(u));
    return r;
}
__device__ __forceinline__ void unpack2(unsigned long long v, float& lo, float& hi) {
    unsigned a, b;
    asm("mov.b64 {%0, %1}, %2;" : "=r"(a), "=r"(b) : "l"(v));
    lo = __uint_as_float(a); hi = __uint_as_float(b);
}

// ---------------- GEMM: C(MxDD)=A@B; 64x64 tile; 512 thr = 2 K-teams of 256 ----------------
// Warp mapping: tx = ((t>>5)&1)*8 + (t&7), ty = (t>>6)*4 + ((t>>3)&3)
// -> per warp-kk: sA 1 broadcast wavefront, sB 1 wavefront.
// Inner loop is register-software-pipelined at depth 2: iteration kk preloads the
// operands of kk+2 before issuing kk's FFMA2 block, hiding the 29-cyc LDS latency.
// Team 0 sums k in [0,512), team 1 in [512,1024); deterministic lo+hi combine via pad.
// mode 0: C = v
// mode 1: C(=P4) = v;  W = I/24 + P/120 + P2/720 + P3/5040 + v/40320
// mode 2: C(=E)  = v + I + P + P2/2 + P3/6
__device__ __forceinline__ void gemm_tile512(
    const float* __restrict__ A, const float* __restrict__ B, float* __restrict__ C,
    int M, int row0, int bx, int mode,
    const float* __restrict__ P, const float* __restrict__ P2,
    const float* __restrict__ P3, float* __restrict__ W)
{
    __shared__ float smem[2][2][GBK][64];     // [team][A|B][k][64] = 16KB
    float* pad = &smem[0][0][0][0];           // aliased 64x64 partial pad (used after final sync)
    int tid = threadIdx.x;
    int team = tid >> 8;
    int t = tid & 255;
    int tx = ((t >> 5) & 1) * 8 + (t & 7);
    int ty = (t >> 6) * 4 + ((t >> 3) & 3);
    int k0 = team << 9;
    float (*sA)[64] = smem[team][0];
    float (*sB)[64] = smem[team][1];

    unsigned long long acc[4][2];
    #pragma unroll
    for (int i = 0; i < 4; i++) { acc[i][0] = 0ULL; acc[i][1] = 0ULL; }

    for (int kt = 0; kt < 512; kt += GBK) {
        {   // stage A tile (transposed)
            int r = t >> 2, kc = t & 3;
            float4 v = make_float4(0.f, 0.f, 0.f, 0.f);
            if (row0 + r < M)
                v = *(const float4*)&A[(size_t)(row0 + r) * DD + k0 + kt + kc * 4];
            sA[kc * 4 + 0][r] = v.x;
            sA[kc * 4 + 1][r] = v.y;
            sA[kc * 4 + 2][r] = v.z;
            sA[kc * 4 + 3][r] = v.w;
        }
        {   // stage B tile
            int k = t >> 4, nc = t & 15;
            *(float4*)&sB[k][nc * 4] =
                *(const float4*)&B[(size_t)(k0 + kt + k) * DD + bx * 64 + nc * 4];
        }
        __syncthreads();

        // software-pipelined inner loop, prefetch depth 2
        float4      a0 = *(const float4*)&sA[0][ty * 4];
        ulonglong2  b0 = *(const ulonglong2*)&sB[0][tx * 4];
        float4      a1 = *(const float4*)&sA[1][ty * 4];
        ulonglong2  b1 = *(const ulonglong2*)&sB[1][tx * 4];
        #pragma unroll
        for (int kk = 0; kk < GBK; kk++) {
            float4 an; ulonglong2 bn;
            if (kk + 2 < GBK) {
                an = *(const float4*)&sA[kk + 2][ty * 4];
                bn = *(const ulonglong2*)&sB[kk + 2][tx * 4];
            }
            unsigned long long p0 = pack2(a0.x), p1 = pack2(a0.y),
                               p2 = pack2(a0.z), p3 = pack2(a0.w);
            ffma2(acc[0][0], p0, b0.x); ffma2(acc[0][1], p0, b0.y);
            ffma2(acc[1][0], p1, b0.x); ffma2(acc[1][1], p1, b0.y);
            ffma2(acc[2][0], p2, b0.x); ffma2(acc[2][1], p2, b0.y);
            ffma2(acc[3][0], p3, b0.x); ffma2(acc[3][1], p3, b0.y);
            a0 = a1; b0 = b1;
            if (kk + 2 < GBK) { a1 = an; b1 = bn; }
        }
        __syncthreads();
    }

    // combine: team 1 deposits its partials, team 0 adds (lo-half + hi-half, deterministic)
    if (team == 1) {
        #pragma unroll
        for (int i = 0; i < 4; i++) {
            float v[4];
            unpack2(acc[i][0], v[0], v[1]);
            unpack2(acc[i][1], v[2], v[3]);
            *(float4*)&pad[(ty * 4 + i) * 64 + tx * 4] = make_float4(v[0], v[1], v[2], v[3]);
        }
    }
    __syncthreads();
    if (team == 0) {
        #pragma unroll
        for (int i = 0; i < 4; i++) {
            int r = row0 + ty * 4 + i;
            if (r >= M) continue;
            float v[4];
            unpack2(acc[i][0], v[0], v[1]);
            unpack2(acc[i][1], v[2], v[3]);
            float4 pv = *(const float4*)&pad[(ty * 4 + i) * 64 + tx * 4];
            v[0] += pv.x; v[1] += pv.y; v[2] += pv.z; v[3] += pv.w;
            int c0 = bx * 64 + tx * 4;
            size_t base = (size_t)r * DD + c0;
            if (mode == 0) {
                *(float4*)&C[base] = make_float4(v[0], v[1], v[2], v[3]);
            } else if (mode == 1) {
                *(float4*)&C[base] = make_float4(v[0], v[1], v[2], v[3]);
                float w[4];
                #pragma unroll
                for (int j = 0; j < 4; j++) {
                    w[j] = (1.0f/120.0f) * P[base + j] + (1.0f/720.0f) * P2[base + j]
                         + (1.0f/5040.0f) * P3[base + j] + (1.0f/40320.0f) * v[j];
                    if (r == c0 + j) w[j] += 1.0f/24.0f;
                }
                *(float4*)&W[base] = make_float4(w[0], w[1], w[2], w[3]);
            } else {
                float e[4];
                #pragma unroll
                for (int j = 0; j < 4; j++) {
                    e[j] = v[j] + P[base + j] + 0.5f * P2[base + j]
                         + (1.0f/6.0f) * P3[base + j];
                    if (r == c0 + j) e[j] += 1.0f;
                }
                *(float4*)&C[base] = make_float4(e[0], e[1], e[2], e[3]);
            }
        }
    }
}

__global__ void __launch_bounds__(512, 2) k_gemm512(
    const float* __restrict__ A, const float* __restrict__ B, float* __restrict__ C,
    int M, int mode, const float* __restrict__ P, const float* __restrict__ P2,
    const float* __restrict__ P3, float* __restrict__ W)
{
    gemm_tile512(A, B, C, M, blockIdx.y * 64, blockIdx.x, mode, P, P2, P3, W);
}

// fused: by<16 squares (Bn = Bc@Bc); by>=16 doubles rows (Adst = Ar@Bc)
__global__ void __launch_bounds__(512, 2) k_sq_dbl512(
    const float* __restrict__ Bc, float* __restrict__ Bn,
    const float* __restrict__ Ar, float* __restrict__ Adst, int rows)
{
    if (blockIdx.y < 16)
        gemm_tile512(Bc, Bc, Bn, DD, blockIdx.y * 64, blockIdx.x, 0, 0, 0, 0, 0);
    else
        gemm_tile512(Ar, Bc, Adst, rows, (blockIdx.y - 16) * 64, blockIdx.x, 0, 0, 0, 0, 0);
}

__global__ void k_getcol(const float* __restrict__ Bc, float* __restrict__ u) {
    u[threadIdx.x] = Bc[(size_t)threadIdx.x * DD + 16];
}

// fused tail step: blocks [0,256) do col-16 gemv (Arows[ofs+b][16] = Arows[b].u);
// blocks [256,1280) do matvec row (u_out[b-256] = Bc[b-256].u). Both only READ u.
__global__ void __launch_bounds__(256) k_tail(
    const float* __restrict__ Bc, const float* __restrict__ u,
    float* __restrict__ u_out, int ofs)
{
    __shared__ float red[256];
    int b = blockIdx.x, t = threadIdx.x;
    const float* row = (b < 256) ? &d_Arows[(size_t)b * DD]
                                 : &Bc[(size_t)(b - 256) * DD];
    float s = 0.0f;
    for (int k = t; k < DD; k += 256)
        s = fmaf(row[k], u[k], s);
    red[t] = s;
    __syncthreads();
    for (int w = 128; w > 0; w >>= 1) {
        if (t < w) red[t] += red[t + w];
        __syncthreads();
    }
    if (t == 0) {
        if (b < 256) d_Arows[(size_t)(ofs + b) * DD + 16] = red[0];
        else         u_out[b - 256] = red[0];
    }
}

// ---------------- driver ----------------
extern "C" void kernel_launch(void* const* d_in, const int* in_sizes, int n_in,
                              void* d_out, int out_size) {
    const float* log_g = (const float*)d_in[0];
    int n_steps = out_size / 3;
    if (n_steps < 1) n_steps = 1;
    if (n_steps > 1024) n_steps = 1024;

    void *p0, *p1, *p2, *p3, *p4, *pA, *pua, *pub;
    cudaGetSymbolAddress(&p0, d_M0);
    cudaGetSymbolAddress(&p1, d_M1);
    cudaGetSymbolAddress(&p2, d_M2);
    cudaGetSymbolAddress(&p3, d_M3);
    cudaGetSymbolAddress(&p4, d_M4);
    cudaGetSymbolAddress(&pA, d_Arows);
    cudaGetSymbolAddress(&pua, d_ua);
    cudaGetSymbolAddress(&pub, d_ub);
    float *M0 = (float*)p0, *M1 = (float*)p1, *M2 = (float*)p2,
          *M3 = (float*)p3, *M4 = (float*)p4, *Ar = (float*)pA;
    float *ua = (float*)pua, *ub = (float*)pub;

    // Phase 0: build generator P (fp32, scale 1/(4*HBAR)) in M0
    k_build_H<<<1, 1024>>>(log_g);
    k_stageG<<<1024, 1024>>>();
    k_project<<<1024, 1024>>>();

    dim3 gfull(16, 16);
    // Phase 1: expm = order-8 Taylor (Paterson-Stockmeyer) + 2 squarings
    k_gemm512<<<gfull, 512>>>(M0, M0, M1, DD, 0, 0, 0, 0, 0);       // P2 -> M1
    k_gemm512<<<gfull, 512>>>(M1, M0, M2, DD, 0, 0, 0, 0, 0);       // P3 -> M2
    k_gemm512<<<gfull, 512>>>(M1, M1, M4, DD, 1, M0, M1, M2, M3);   // P4 -> M4, W -> M3
    k_gemm512<<<gfull, 512>>>(M4, M3, M1, DD, 2, M0, M1, M2, 0);    // E = P4@W + C1 -> M1
    k_gemm512<<<gfull, 512>>>(M1, M1, M3, DD, 0, 0, 0, 0, 0);       // E^2 -> M3
    k_gemm512<<<gfull, 512>>>(M3, M3, M1, DD, 0, 0, 0, 0, 0);       // U = E^4 -> M1

    // Phase 2: time doubling up to 256 rows (times 0..127), 7 fused iterations
    k_Ainit<<<2, 1024>>>();
    float* Bc = M1;   // U
    float* Bn = M3;
    int rows = 2;
    for (int kd = 0; kd < 7; kd++) {
        int dbl_tiles = (rows + 63) / 64;
        k_sq_dbl512<<<dim3(16, 16 + dbl_tiles), 512>>>(
            Bc, Bn, Ar, Ar + (size_t)rows * DD, rows);
        rows <<= 1;
        float* tmp = Bc; Bc = Bn; Bn = tmp;
    }
    // Bc = U^128, rows = 256 (times 0..127 fully materialized)

    // Phase 3: tail — times 128..1023 need only column 16.
    // u_k = col16 of U^(128k);  Arows[256k + b][16] = Arows[b] . u_k
    k_getcol<<<1, 1024>>>(Bc, ua);
    float* ucur = ua;
    float* unxt = ub;
    for (int k = 1; k <= 7; k++) {
        int nblocks = (k < 7) ? 1280 : 256;   // fuse gemv + matvec while matvec still needed
        k_tail<<<nblocks, 256>>>(Bc, ucur, unxt, 256 * k);
        float* tmp = ucur; ucur = unxt; unxt = tmp;
    }

    // Phase 4: extract populations
    k_extract<<<(n_steps + 255) / 256, 256>>>((float*)d_out, n_steps);
}

// round 14
// speedup vs baseline: 1.8419x; 1.4140x over previous
#include <cuda_runtime.h>
#include <math.h>

#define DD 1024
#define GBK 16
#define NW 48   // CSR row width cap (analytic max nnz/row ~21)

// ---------------- static device storage (no allocation allowed) ----------------
static __device__ double d_H[32 * 32];
static __device__ double d_g;
static __device__ double d_CS[DD * DD];
static __device__ double d_CA[DD * DD];
static __device__ float  d_M0[DD * DD];     // dense P (scale 1/(2*HBAR))
static __device__ float  d_M1[DD * DD];     // Horner ping / U
static __device__ float  d_M3[DD * DD];     // Horner pong / E / ping
static __device__ int    d_cidx[DD * NW];
static __device__ float  d_cval[DD * NW];
static __device__ int    d_cnt[DD];
static __device__ float  d_ua[DD];
static __device__ float  d_ub[DD];
static __device__ float  d_Arows[2048 * DD];

// ---------------- model: H on reduced 32-dim space ----------------
__device__ __forceinline__ double qmat(int r, int c) {
    if (c == r + 1) return sqrt((double)c * 0.5);
    if (r == c + 1) return sqrt((double)r * 0.5);
    return 0.0;
}

__global__ void k_build_H(const float* log_g) {
    int a = threadIdx.x;
    if (a == 0) d_g = (double)expf(log_g[0]);
    int i = a >> 5, j = a & 31;
    int si = i >> 4, vi = i & 15, v6i = vi >> 2, v10i = vi & 3;
    int sj = j >> 4, vj = j & 15, v6j = vj >> 2, v10j = vj & 3;
    const double CM2EV = 0.00012398419;
    const double E_S1 = 3.995, E_S2 = 4.9183;
    const double om6a = 596.0 * CM2EV, om10a = 919.0 * CM2EV;
    const double kap1 = -0.0964, kap2 = 0.1193;
    const double lam = 0.1825, gam = -0.018;
    double val = 0.0;
    if (si == sj) {
        if (vi == vj) val += (si == 0 ? E_S1 : E_S2) + om6a * v6i + om10a * v10i;
        if (v10i == v10j) val += (si == 0 ? kap1 : kap2) * qmat(v6i, v6j);
    } else {
        if (v6i == v6j) {
            double q2 = 0.0;
            #pragma unroll
            for (int m = 0; m < 4; m++) q2 += qmat(v10i, m) * qmat(m, v10j);
            val += lam * qmat(v10i, v10j) + gam * q2;
        }
    }
    d_H[i * 32 + j] = val;
}

// ---------------- real hermitian basis bookkeeping ----------------
__device__ __forceinline__ void decode_basis(int m, int& type, int& p, int& q) {
    if (m < 32) { type = 0; p = q = m; return; }
    int pi = (m < 528) ? (m - 32) : (m - 528);
    type = (m < 528) ? 1 : 2;
    int r = 0, cnt = 31;
    while (pi >= cnt) { pi -= cnt; r++; cnt--; }
    p = r; q = r + 1 + pi;
}

__global__ void k_stageG() {
    int n = blockIdx.x;
    int ab = threadIdx.x;
    int a = ab >> 5, b = ab & 31;
    int type, p, q;
    decode_basis(n, type, p, q);
    double v = (type == 0) ? 1.0 : 0.70710678118654752440;
    int nc = (type == 0) ? 1 : 2;
    int cc[2] = { p, q };
    int dd[2] = { q, p };
    double ww[2] = { v, (type == 2) ? -v : v };

    const double g = d_g;
    double HX = 0.0, XH = 0.0, Xab = 0.0, X16 = 0.0;
    for (int e = 0; e < nc; e++) {
        if (dd[e] == b) HX += d_H[a * 32 + cc[e]] * ww[e];
        if (cc[e] == a) XH += ww[e] * d_H[dd[e] * 32 + b];
        if (cc[e] == a && dd[e] == b) Xab += ww[e];
        if (a < 16 && b < 16 && cc[e] == a + 16 && dd[e] == b + 16) X16 += ww[e];
    }
    double diss = g * (X16 - 0.5 * Xab * (double)((a >= 16) + (b >= 16)));
    double cs, ca;
    if (type == 2) { cs = XH - HX; ca = diss; }
    else           { ca = HX - XH; cs = diss; }
    d_CS[n * DD + ab] = cs;
    d_CA[n * DD + ab] = ca;
}

// scale = (DT/HBAR) / 2   (s = 1 squaring; Horner degree 16 for expm)
__global__ void k_project() {
    int idx = blockIdx.x * 1024 + threadIdx.x;
    int m = idx >> 10, n = idx & 1023;
    int type, i, j;
    decode_basis(m, type, i, j);
    const double SQ2 = 1.41421356237309504880;
    double val;
    if (type == 0)      val = d_CS[n * DD + i * 33];
    else if (type == 1) val = SQ2 * d_CS[n * DD + i * 32 + j];
    else                val = SQ2 * d_CA[n * DD + i * 32 + j];
    const double scale = (1.0 / 0.6582119569) / 2.0;
    d_M0[m * DD + n] = (float)(val * scale);
}

// ---------------- CSR build (deterministic ballot-scan compaction) ----------------
__global__ void k_tocsr() {
    int m = blockIdx.x;
    int n = threadIdx.x;
    float v = d_M0[m * DD + n];
    bool nz = (v != 0.0f);
    unsigned mask = __ballot_sync(0xffffffffu, nz);
    int lane = n & 31, w = n >> 5;
    __shared__ int wcnt[32];
    __shared__ int woff[32];
    __shared__ int tot;
    if (lane == 0) wcnt[w] = __popc(mask);
    __syncthreads();
    if (n == 0) {
        int s = 0;
        for (int i = 0; i < 32; i++) { woff[i] = s; s += wcnt[i]; }
        tot = (s > NW) ? NW : s;
        d_cnt[m] = tot;
    }
    __syncthreads();
    if (nz) {
        int pos = woff[w] + __popc(mask & ((1u << lane) - 1u));
        if (pos < NW) {
            d_cidx[m * NW + pos] = n;
            d_cval[m * NW + pos] = v;
        }
    }
    if (n >= tot && n < NW) {        // pad
        d_cidx[m * NW + n] = 0;
        d_cval[m * NW + n] = 0.0f;
    }
}

// T0 = I + P/16  (Horner init)
__global__ void k_hinit(float* __restrict__ T) {
    int idx = blockIdx.x * 1024 + threadIdx.x;
    int r = idx >> 10, c = idx & 1023;
    float x = d_M0[idx] * (1.0f / 16.0f);
    if (r == c) x += 1.0f;
    T[idx] = x;
}

// Horner step: Y = I + (P @ X) / k   (P sparse, CSR rows; ascending-n order)
__global__ void __launch_bounds__(256) k_spmm(
    const float* __restrict__ X, float* __restrict__ Y, float invk)
{
    int m = blockIdx.x;
    int t = threadIdx.x;
    __shared__ int   sidx[NW];
    __shared__ float sval[NW];
    __shared__ int   scnt;
    if (t < NW) { sidx[t] = d_cidx[m * NW + t]; sval[t] = d_cval[m * NW + t]; }
    if (t == 0) scnt = d_cnt[m];
    __syncthreads();
    int cnt = scnt;
    int c = t * 4;
    float4 acc = make_float4(0.f, 0.f, 0.f, 0.f);
    for (int e = 0; e < cnt; e++) {
        float v = sval[e];
        const float4 x = *(const float4*)&X[(size_t)sidx[e] * DD + c];
        acc.x = fmaf(v, x.x, acc.x);
        acc.y = fmaf(v, x.y, acc.y);
        acc.z = fmaf(v, x.z, acc.z);
        acc.w = fmaf(v, x.w, acc.w);
    }
    float4 y = make_float4(acc.x * invk, acc.y * invk, acc.z * invk, acc.w * invk);
    int d = m - c;
    if (d >= 0 && d < 4) ((float*)&y)[d] += 1.0f;
    *(float4*)&Y[(size_t)m * DD + c] = y;
}

__global__ void k_Ainit() {
    int r = blockIdx.x, c = threadIdx.x;
    float v = 0.0f;
    if (r == 0 && c < 16) v = 1.0f;
    if (r == 1 && c >= 16 && c < 32) v = 1.0f;
    d_Arows[r * DD + c] = v;
}

__global__ void k_extract(float* __restrict__ out, int n) {
    int t = blockIdx.x * blockDim.x + threadIdx.x;
    if (t >= n) return;
    out[t] = 0.0f;
    out[n + t]     = d_Arows[(size_t)(2 * t) * DD + 16];
    out[2 * n + t] = d_Arows[(size_t)(2 * t + 1) * DD + 16];
}

// ---------------- packed f32x2 helpers ----------------
__device__ __forceinline__ void ffma2(unsigned long long& acc,
                                      unsigned long long a, unsigned long long b) {
    asm("fma.rn.f32x2 %0, %1, %2, %0;" : "+l"(acc) : "l"(a), "l"(b));
}
__device__ __forceinline__ unsigned long long pack2(float x) {
    unsigned long long r; unsigned u = __float_as_uint(x);
    asm("mov.b64 %0, {%1, %1};" : "=l"(r) : "r"(u));
    return r;
}
__device__ __forceinline__ void unpack2(unsigned long long v, float& lo, float& hi) {
    unsigned a, b;
    asm("mov.b64 {%0, %1}, %2;" : "=r"(a), "=r"(b) : "l"(v));
    lo = __uint_as_float(a); hi = __uint_as_float(b);
}

// ---------------- dense GEMM: C(MxDD)=A@B; 64x64 tile; 512 thr = 2 K-teams ----------------
// (round-11 engine: warp-shape-aware mapping, deterministic split-K combine)
__device__ __forceinline__ void gemm_tile512(
    const float* __restrict__ A, const float* __restrict__ B, float* __restrict__ C,
    int M, int row0, int bx)
{
    __shared__ float smem[2][2][GBK][64];
    float* pad = &smem[0][0][0][0];
    int tid = threadIdx.x;
    int team = tid >> 8;
    int t = tid & 255;
    int tx = ((t >> 5) & 1) * 8 + (t & 7);
    int ty = (t >> 6) * 4 + ((t >> 3) & 3);
    int k0 = team << 9;
    float (*sA)[64] = smem[team][0];
    float (*sB)[64] = smem[team][1];

    unsigned long long acc[4][2];
    #pragma unroll
    for (int i = 0; i < 4; i++) { acc[i][0] = 0ULL; acc[i][1] = 0ULL; }

    for (int kt = 0; kt < 512; kt += GBK) {
        {
            int r = t >> 2, kc = t & 3;
            float4 v = make_float4(0.f, 0.f, 0.f, 0.f);
            if (row0 + r < M)
                v = *(const float4*)&A[(size_t)(row0 + r) * DD + k0 + kt + kc * 4];
            sA[kc * 4 + 0][r] = v.x;
            sA[kc * 4 + 1][r] = v.y;
            sA[kc * 4 + 2][r] = v.z;
            sA[kc * 4 + 3][r] = v.w;
        }
        {
            int k = t >> 4, nc = t & 15;
            *(float4*)&sB[k][nc * 4] =
                *(const float4*)&B[(size_t)(k0 + kt + k) * DD + bx * 64 + nc * 4];
        }
        __syncthreads();
        #pragma unroll
        for (int kk = 0; kk < GBK; kk++) {
            float4 av = *(const float4*)&sA[kk][ty * 4];
            ulonglong2 bv = *(const ulonglong2*)&sB[kk][tx * 4];
            unsigned long long a0 = pack2(av.x), a1 = pack2(av.y),
                               a2 = pack2(av.z), a3 = pack2(av.w);
            ffma2(acc[0][0], a0, bv.x); ffma2(acc[0][1], a0, bv.y);
            ffma2(acc[1][0], a1, bv.x); ffma2(acc[1][1], a1, bv.y);
            ffma2(acc[2][0], a2, bv.x); ffma2(acc[2][1], a2, bv.y);
            ffma2(acc[3][0], a3, bv.x); ffma2(acc[3][1], a3, bv.y);
        }
        __syncthreads();
    }

    if (team == 1) {
        #pragma unroll
        for (int i = 0; i < 4; i++) {
            float v[4];
            unpack2(acc[i][0], v[0], v[1]);
            unpack2(acc[i][1], v[2], v[3]);
            *(float4*)&pad[(ty * 4 + i) * 64 + tx * 4] = make_float4(v[0], v[1], v[2], v[3]);
        }
    }
    __syncthreads();
    if (team == 0) {
        #pragma unroll
        for (int i = 0; i < 4; i++) {
            int r = row0 + ty * 4 + i;
            if (r >= M) continue;
            float v[4];
            unpack2(acc[i][0], v[0], v[1]);
            unpack2(acc[i][1], v[2], v[3]);
            float4 pv = *(const float4*)&pad[(ty * 4 + i) * 64 + tx * 4];
            v[0] += pv.x; v[1] += pv.y; v[2] += pv.z; v[3] += pv.w;
            *(float4*)&C[(size_t)r * DD + bx * 64 + tx * 4] =
                make_float4(v[0], v[1], v[2], v[3]);
        }
    }
}

__global__ void __launch_bounds__(512, 2) k_gemm512(
    const float* __restrict__ A, const float* __restrict__ B, float* __restrict__ C, int M)
{
    gemm_tile512(A, B, C, M, blockIdx.y * 64, blockIdx.x);
}

// fused: by<16 squares (Bn = Bc@Bc); by>=16 doubles rows (Adst = Ar@Bc)
__global__ void __launch_bounds__(512, 2) k_sq_dbl512(
    const float* __restrict__ Bc, float* __restrict__ Bn,
    const float* __restrict__ Ar, float* __restrict__ Adst, int rows)
{
    if (blockIdx.y < 16)
        gemm_tile512(Bc, Bc, Bn, DD, blockIdx.y * 64, blockIdx.x);
    else
        gemm_tile512(Ar, Bc, Adst, rows, (blockIdx.y - 16) * 64, blockIdx.x);
}

__global__ void k_getcol(const float* __restrict__ Bc, float* __restrict__ u) {
    u[threadIdx.x] = Bc[(size_t)threadIdx.x * DD + 16];
}

// fused tail step: blocks [0,256) col-16 gemv; blocks [256,1280) matvec row.
__global__ void __launch_bounds__(256) k_tail(
    const float* __restrict__ Bc, const float* __restrict__ u,
    float* __restrict__ u_out, int ofs)
{
    __shared__ float red[256];
    int b = blockIdx.x, t = threadIdx.x;
    const float* row = (b < 256) ? &d_Arows[(size_t)b * DD]
                                 : &Bc[(size_t)(b - 256) * DD];
    float s = 0.0f;
    for (int k = t; k < DD; k += 256)
        s = fmaf(row[k], u[k], s);
    red[t] = s;
    __syncthreads();
    for (int w = 128; w > 0; w >>= 1) {
        if (t < w) red[t] += red[t + w];
        __syncthreads();
    }
    if (t == 0) {
        if (b < 256) d_Arows[(size_t)(ofs + b) * DD + 16] = red[0];
        else         u_out[b - 256] = red[0];
    }
}

// ---------------- driver ----------------
extern "C" void kernel_launch(void* const* d_in, const int* in_sizes, int n_in,
                              void* d_out, int out_size) {
    const float* log_g = (const float*)d_in[0];
    int n_steps = out_size / 3;
    if (n_steps < 1) n_steps = 1;
    if (n_steps > 1024) n_steps = 1024;

    void *p1, *p3, *pA, *pua, *pub;
    cudaGetSymbolAddress(&p1, d_M1);
    cudaGetSymbolAddress(&p3, d_M3);
    cudaGetSymbolAddress(&pA, d_Arows);
    cudaGetSymbolAddress(&pua, d_ua);
    cudaGetSymbolAddress(&pub, d_ub);
    float *M1 = (float*)p1, *M3 = (float*)p3, *Ar = (float*)pA;
    float *ua = (float*)pua, *ub = (float*)pub;

    // Phase 0: build generator P (fp32, scale 1/(2*HBAR)), compress to CSR
    k_build_H<<<1, 1024>>>(log_g);
    k_stageG<<<1024, 1024>>>();
    k_project<<<1024, 1024>>>();
    k_tocsr<<<1024, 1024>>>();

    // Phase 1: E = expm(P) via degree-16 Horner with SPARSE P, then U = E^2
    k_hinit<<<1024, 1024>>>(M1);                 // T = I + P/16
    float* Tc = M1; float* Tn = M3;
    for (int k = 15; k >= 1; k--) {
        k_spmm<<<1024, 256>>>(Tc, Tn, 1.0f / (float)k);
        float* tmp = Tc; Tc = Tn; Tn = tmp;
    }
    // Tc = E (in M3 after 15 odd steps). U = E@E -> the other buffer.
    dim3 gfull(16, 16);
    k_gemm512<<<gfull, 512>>>(Tc, Tc, Tn, DD);   // U -> Tn
    float* Bc = Tn;
    float* Bn = Tc;

    // Phase 2: time doubling up to 256 rows (times 0..127), 7 fused iterations
    k_Ainit<<<2, 1024>>>();
    int rows = 2;
    for (int kd = 0; kd < 7; kd++) {
        int dbl_tiles = (rows + 63) / 64;
        k_sq_dbl512<<<dim3(16, 16 + dbl_tiles), 512>>>(
            Bc, Bn, Ar, Ar + (size_t)rows * DD, rows);
        rows <<= 1;
        float* tmp = Bc; Bc = Bn; Bn = tmp;
    }
    // Bc = U^128, rows = 256 (times 0..127 fully materialized)

    // Phase 3: tail — times 128..1023 need only column 16.
    k_getcol<<<1, 1024>>>(Bc, ua);
    float* ucur = ua;
    float* unxt = ub;
    for (int k = 1; k <= 7; k++) {
        int nblocks = (k < 7) ? 1280 : 256;
        k_tail<<<nblocks, 256>>>(Bc, ucur, unxt, 256 * k);
        float* tmp = ucur; ucur = unxt; unxt = tmp;
    }

    // Phase 4: extract populations
    k_extract<<<(n_steps + 255) / 256, 256>>>((float*)d_out, n_steps);
}

// round 16
// speedup vs baseline: 1.9381x; 1.0522x over previous
#include <cuda_runtime.h>
#include <math.h>

#define DD 1024
#define GBK 16
#define SAS 68   // padded smem row stride (floats): mult of 4 (alignment), 68%32=4 -> 2-way staging conflicts (was 4-way)
#define NW 48    // CSR row width cap (analytic max nnz/row ~21)

// ---------------- static device storage (no allocation allowed) ----------------
static __device__ double d_H[32 * 32];
static __device__ double d_g;
static __device__ float  d_M0[DD * DD];     // dense P (scale 1/(2*HBAR))
static __device__ float  d_M1[DD * DD];     // Horner ping / U
static __device__ float  d_M3[DD * DD];     // Horner pong / E / ping
static __device__ int    d_cidx[DD * NW];
static __device__ float  d_cval[DD * NW];
static __device__ int    d_cnt[DD];
static __device__ float  d_ua[DD];
static __device__ float  d_ub[DD];
static __device__ float  d_Arows[2048 * DD];

// ---------------- model: H on reduced 32-dim space ----------------
__device__ __forceinline__ double qmat(int r, int c) {
    if (c == r + 1) return sqrt((double)c * 0.5);
    if (r == c + 1) return sqrt((double)r * 0.5);
    return 0.0;
}

__global__ void k_build_H(const float* log_g) {
    int a = threadIdx.x;
    if (a == 0) d_g = (double)expf(log_g[0]);
    int i = a >> 5, j = a & 31;
    int si = i >> 4, vi = i & 15, v6i = vi >> 2, v10i = vi & 3;
    int sj = j >> 4, vj = j & 15, v6j = vj >> 2, v10j = vj & 3;
    const double CM2EV = 0.00012398419;
    const double E_S1 = 3.995, E_S2 = 4.9183;
    const double om6a = 596.0 * CM2EV, om10a = 919.0 * CM2EV;
    const double kap1 = -0.0964, kap2 = 0.1193;
    const double lam = 0.1825, gam = -0.018;
    double val = 0.0;
    if (si == sj) {
        if (vi == vj) val += (si == 0 ? E_S1 : E_S2) + om6a * v6i + om10a * v10i;
        if (v10i == v10j) val += (si == 0 ? kap1 : kap2) * qmat(v6i, v6j);
    } else {
        if (v6i == v6j) {
            double q2 = 0.0;
            #pragma unroll
            for (int m = 0; m < 4; m++) q2 += qmat(v10i, m) * qmat(m, v10j);
            val += lam * qmat(v10i, v10j) + gam * q2;
        }
    }
    d_H[i * 32 + j] = val;
}

// ---------------- real hermitian basis bookkeeping ----------------
__device__ __forceinline__ void decode_basis(int m, int& type, int& p, int& q) {
    if (m < 32) { type = 0; p = q = m; return; }
    int pi = (m < 528) ? (m - 32) : (m - 528);
    type = (m < 528) ? 1 : 2;
    int r = 0, cnt = 31;
    while (pi >= cnt) { pi -= cnt; r++; cnt--; }
    p = r; q = r + 1 + pi;
}

// Fused stageG+project: P[m,n] directly (same double op sequence as the two-kernel
// version). scale = (DT/HBAR)/2  (s = 1 squaring; Horner degree 16 for expm)
__global__ void k_buildP() {
    int m = blockIdx.x;
    int n = threadIdx.x;
    int tm, i, j;
    decode_basis(m, tm, i, j);
    int tn, p, q;
    decode_basis(n, tn, p, q);
    int a = i, b = j;
    double v = (tn == 0) ? 1.0 : 0.70710678118654752440;
    int nc = (tn == 0) ? 1 : 2;
    int cc[2] = { p, q };
    int dd[2] = { q, p };
    double ww[2] = { v, (tn == 2) ? -v : v };

    const double g = d_g;
    double HX = 0.0, XH = 0.0, Xab = 0.0, X16 = 0.0;
    for (int e = 0; e < nc; e++) {
        if (dd[e] == b) HX += d_H[a * 32 + cc[e]] * ww[e];
        if (cc[e] == a) XH += ww[e] * d_H[dd[e] * 32 + b];
        if (cc[e] == a && dd[e] == b) Xab += ww[e];
        if (a < 16 && b < 16 && cc[e] == a + 16 && dd[e] == b + 16) X16 += ww[e];
    }
    double diss = g * (X16 - 0.5 * Xab * (double)((a >= 16) + (b >= 16)));
    double cs, ca;
    if (tn == 2) { cs = XH - HX; ca = diss; }
    else         { ca = HX - XH; cs = diss; }

    const double SQ2 = 1.41421356237309504880;
    double val;
    if (tm == 0)      val = cs;
    else if (tm == 1) val = SQ2 * cs;
    else              val = SQ2 * ca;
    const double scale = (1.0 / 0.6582119569) / 2.0;
    d_M0[m * DD + n] = (float)(val * scale);
}

// ---------------- CSR build (deterministic ballot-scan compaction) ----------------
__global__ void k_tocsr() {
    int m = blockIdx.x;
    int n = threadIdx.x;
    float v = d_M0[m * DD + n];
    bool nz = (v != 0.0f);
    unsigned mask = __ballot_sync(0xffffffffu, nz);
    int lane = n & 31, w = n >> 5;
    __shared__ int wcnt[32];
    __shared__ int woff[32];
    __shared__ int tot;
    if (lane == 0) wcnt[w] = __popc(mask);
    __syncthreads();
    if (n == 0) {
        int s = 0;
        for (int i = 0; i < 32; i++) { woff[i] = s; s += wcnt[i]; }
        tot = (s > NW) ? NW : s;
        d_cnt[m] = tot;
    }
    __syncthreads();
    if (nz) {
        int pos = woff[w] + __popc(mask & ((1u << lane) - 1u));
        if (pos < NW) {
            d_cidx[m * NW + pos] = n;
            d_cval[m * NW + pos] = v;
        }
    }
    if (n >= tot && n < NW) {
        d_cidx[m * NW + n] = 0;
        d_cval[m * NW + n] = 0.0f;
    }
}

// T0 = I + P/16  (Horner init)
__global__ void k_hinit(float* __restrict__ T) {
    int idx = blockIdx.x * 1024 + threadIdx.x;
    int r = idx >> 10, c = idx & 1023;
    float x = d_M0[idx] * (1.0f / 16.0f);
    if (r == c) x += 1.0f;
    T[idx] = x;
}

// Horner step: Y = I + (P @ X) / k   (P sparse, CSR rows; ascending-n order)
__global__ void __launch_bounds__(256) k_spmm(
    const float* __restrict__ X, float* __restrict__ Y, float invk)
{
    int m = blockIdx.x;
    int t = threadIdx.x;
    __shared__ int   sidx[NW];
    __shared__ float sval[NW];
    __shared__ int   scnt;
    if (t < NW) { sidx[t] = d_cidx[m * NW + t]; sval[t] = d_cval[m * NW + t]; }
    if (t == 0) scnt = d_cnt[m];
    __syncthreads();
    int cnt = scnt;
    int c = t * 4;
    float4 acc = make_float4(0.f, 0.f, 0.f, 0.f);
    for (int e = 0; e < cnt; e++) {
        float v = sval[e];
        const float4 x = *(const float4*)&X[(size_t)sidx[e] * DD + c];
        acc.x = fmaf(v, x.x, acc.x);
        acc.y = fmaf(v, x.y, acc.y);
        acc.z = fmaf(v, x.z, acc.z);
        acc.w = fmaf(v, x.w, acc.w);
    }
    float4 y = make_float4(acc.x * invk, acc.y * invk, acc.z * invk, acc.w * invk);
    int d = m - c;
    if (d >= 0 && d < 4) ((float*)&y)[d] += 1.0f;
    *(float4*)&Y[(size_t)m * DD + c] = y;
}

__global__ void k_Ainit() {
    int r = blockIdx.x, c = threadIdx.x;
    float v = 0.0f;
    if (r == 0 && c < 16) v = 1.0f;
    if (r == 1 && c >= 16 && c < 32) v = 1.0f;
    d_Arows[r * DD + c] = v;
}

__global__ void k_extract(float* __restrict__ out, int n) {
    int t = blockIdx.x * blockDim.x + threadIdx.x;
    if (t >= n) return;
    out[t] = 0.0f;
    out[n + t]     = d_Arows[(size_t)(2 * t) * DD + 16];
    out[2 * n + t] = d_Arows[(size_t)(2 * t + 1) * DD + 16];
}

// ---------------- packed f32x2 helpers ----------------
__device__ __forceinline__ void ffma2(unsigned long long& acc,
                                      unsigned long long a, unsigned long long b) {
    asm("fma.rn.f32x2 %0, %1, %2, %0;" : "+l"(acc) : "l"(a), "l"(b));
}
__device__ __forceinline__ unsigned long long pack2(float x) {
    unsigned long long r; unsigned u = __float_as_uint(x);
    asm("mov.b64 %0, {%1, %1};" : "=l"(r) : "r"(u));
    return r;
}
__device__ __forceinline__ void unpack2(unsigned long long v, float& lo, float& hi) {
    unsigned a, b;
    asm("mov.b64 {%0, %1}, %2;" : "=r"(a), "=r"(b) : "l"(v));
    lo = __uint_as_float(a); hi = __uint_as_float(b);
}

// ---------------- dense GEMM: C(MxDD)=A@B; 64x64 tile; 512 thr = 2 K-teams ----------------
// smem rows padded to SAS=68 floats (16B-aligned stride): A-staging STS conflicts
// drop 4-way -> 2-way; inner LDS.128 reads stay conflict-free.
__device__ __forceinline__ void gemm_tile512(
    const float* __restrict__ A, const float* __restrict__ B, float* __restrict__ C,
    int M, int row0, int bx)
{
    __shared__ float smem[2 * 2 * GBK * SAS]; // [team][A|B][k][SAS] = 17KB
    float* pad = smem;                         // 64x64 combine pad alias (4096 floats)
    int tid = threadIdx.x;
    int team = tid >> 8;
    int t = tid & 255;
    int tx = ((t >> 5) & 1) * 8 + (t & 7);
    int ty = (t >> 6) * 4 + ((t >> 3) & 3);
    int k0 = team << 9;
    float* sA = smem + team * (2 * GBK * SAS);
    float* sB = sA + GBK * SAS;

    unsigned long long acc[4][2];
    #pragma unroll
    for (int i = 0; i < 4; i++) { acc[i][0] = 0ULL; acc[i][1] = 0ULL; }

    for (int kt = 0; kt < 512; kt += GBK) {
        {   // stage A tile (transposed, padded rows)
            int r = t >> 2, kc = t & 3;
            float4 v = make_float4(0.f, 0.f, 0.f, 0.f);
            if (row0 + r < M)
                v = *(const float4*)&A[(size_t)(row0 + r) * DD + k0 + kt + kc * 4];
            sA[(kc * 4 + 0) * SAS + r] = v.x;
            sA[(kc * 4 + 1) * SAS + r] = v.y;
            sA[(kc * 4 + 2) * SAS + r] = v.z;
            sA[(kc * 4 + 3) * SAS + r] = v.w;
        }
        {   // stage B tile (padded rows)
            int k = t >> 4, nc = t & 15;
            *(float4*)&sB[k * SAS + nc * 4] =
                *(const float4*)&B[(size_t)(k0 + kt + k) * DD + bx * 64 + nc * 4];
        }
        __syncthreads();
        #pragma unroll
        for (int kk = 0; kk < GBK; kk++) {
            float4 av = *(const float4*)&sA[kk * SAS + ty * 4];
            ulonglong2 bv = *(const ulonglong2*)&sB[kk * SAS + tx * 4];
            unsigned long long a0 = pack2(av.x), a1 = pack2(av.y),
                               a2 = pack2(av.z), a3 = pack2(av.w);
            ffma2(acc[0][0], a0, bv.x); ffma2(acc[0][1], a0, bv.y);
            ffma2(acc[1][0], a1, bv.x); ffma2(acc[1][1], a1, bv.y);
            ffma2(acc[2][0], a2, bv.x); ffma2(acc[2][1], a2, bv.y);
            ffma2(acc[3][0], a3, bv.x); ffma2(acc[3][1], a3, bv.y);
        }
        __syncthreads();
    }

    // combine: team 1 deposits partials, team 0 adds (deterministic lo+hi)
    if (team == 1) {
        #pragma unroll
        for (int i = 0; i < 4; i++) {
            float v[4];
            unpack2(acc[i][0], v[0], v[1]);
            unpack2(acc[i][1], v[2], v[3]);
            *(float4*)&pad[(ty * 4 + i) * 64 + tx * 4] = make_float4(v[0], v[1], v[2], v[3]);
        }
    }
    __syncthreads();
    if (team == 0) {
        #pragma unroll
        for (int i = 0; i < 4; i++) {
            int r = row0 + ty * 4 + i;
            if (r >= M) continue;
            float v[4];
            unpack2(acc[i][0], v[0], v[1]);
            unpack2(acc[i][1], v[2], v[3]);
            float4 pv = *(const float4*)&pad[(ty * 4 + i) * 64 + tx * 4];
            v[0] += pv.x; v[1] += pv.y; v[2] += pv.z; v[3] += pv.w;
            *(float4*)&C[(size_t)r * DD + bx * 64 + tx * 4] =
                make_float4(v[0], v[1], v[2], v[3]);
        }
    }
}

__global__ void __launch_bounds__(512, 2) k_gemm512(
    const float* __restrict__ A, const float* __restrict__ B, float* __restrict__ C, int M)
{
    gemm_tile512(A, B, C, M, blockIdx.y * 64, blockIdx.x);
}

// fused: by<16 squares (Bn = Bc@Bc); by>=16 doubles rows (Adst = Ar@Bc)
__global__ void __launch_bounds__(512, 2) k_sq_dbl512(
    const float* __restrict__ Bc, float* __restrict__ Bn,
    const float* __restrict__ Ar, float* __restrict__ Adst, int rows)
{
    if (blockIdx.y < 16)
        gemm_tile512(Bc, Bc, Bn, DD, blockIdx.y * 64, blockIdx.x);
    else
        gemm_tile512(Ar, Bc, Adst, rows, (blockIdx.y - 16) * 64, blockIdx.x);
}

__global__ void k_getcol(const float* __restrict__ Bc, float* __restrict__ u) {
    u[threadIdx.x] = Bc[(size_t)threadIdx.x * DD + 16];
}

// fused tail step: blocks [0,256) col-16 gemv; blocks [256,1280) matvec row.
__global__ void __launch_bounds__(256) k_tail(
    const float* __restrict__ Bc, const float* __restrict__ u,
    float* __restrict__ u_out, int ofs)
{
    __shared__ float red[256];
    int b = blockIdx.x, t = threadIdx.x;
    const float* row = (b < 256) ? &d_Arows[(size_t)b * DD]
                                 : &Bc[(size_t)(b - 256) * DD];
    float s = 0.0f;
    for (int k = t; k < DD; k += 256)
        s = fmaf(row[k], u[k], s);
    red[t] = s;
    __syncthreads();
    for (int w = 128; w > 0; w >>= 1) {
        if (t < w) red[t] += red[t + w];
        __syncthreads();
    }
    if (t == 0) {
        if (b < 256) d_Arows[(size_t)(ofs + b) * DD + 16] = red[0];
        else         u_out[b - 256] = red[0];
    }
}

// ---------------- driver ----------------
extern "C" void kernel_launch(void* const* d_in, const int* in_sizes, int n_in,
                              void* d_out, int out_size) {
    const float* log_g = (const float*)d_in[0];
    int n_steps = out_size / 3;
    if (n_steps < 1) n_steps = 1;
    if (n_steps > 1024) n_steps = 1024;

    void *p1, *p3, *pA, *pua, *pub;
    cudaGetSymbolAddress(&p1, d_M1);
    cudaGetSymbolAddress(&p3, d_M3);
    cudaGetSymbolAddress(&pA, d_Arows);
    cudaGetSymbolAddress(&pua, d_ua);
    cudaGetSymbolAddress(&pub, d_ub);
    float *M1 = (float*)p1, *M3 = (float*)p3, *Ar = (float*)pA;
    float *ua = (float*)pua, *ub = (float*)pub;

    // Phase 0: build generator P (fp32, scale 1/(2*HBAR)) directly; compress to CSR
    k_build_H<<<1, 1024>>>(log_g);
    k_buildP<<<1024, 1024>>>();
    k_tocsr<<<1024, 1024>>>();

    // Phase 1: E = expm(P) via degree-16 Horner with SPARSE P, then U = E^2
    k_hinit<<<1024, 1024>>>(M1);                 // T = I + P/16
    float* Tc = M1; float* Tn = M3;
    for (int k = 15; k >= 1; k--) {
        k_spmm<<<1024, 256>>>(Tc, Tn, 1.0f / (float)k);
        float* tmp = Tc; Tc = Tn; Tn = tmp;
    }
    dim3 gfull(16, 16);
    k_gemm512<<<gfull, 512>>>(Tc, Tc, Tn, DD);   // U -> Tn
    float* Bc = Tn;
    float* Bn = Tc;

    // Phase 2: time doubling up to 256 rows (times 0..127), 7 fused iterations
    k_Ainit<<<2, 1024>>>();
    int rows = 2;
    for (int kd = 0; kd < 7; kd++) {
        int dbl_tiles = (rows + 63) / 64;
        k_sq_dbl512<<<dim3(16, 16 + dbl_tiles), 512>>>(
            Bc, Bn, Ar, Ar + (size_t)rows * DD, rows);
        rows <<= 1;
        float* tmp = Bc; Bc = Bn; Bn = tmp;
    }
    // Bc = U^128, rows = 256 (times 0..127 fully materialized)

    // Phase 3: tail — times 128..1023 need only column 16.
    k_getcol<<<1, 1024>>>(Bc, ua);
    float* ucur = ua;
    float* unxt = ub;
    for (int k = 1; k <= 7; k++) {
        int nblocks = (k < 7) ? 1280 : 256;
        k_tail<<<nblocks, 256>>>(Bc, ucur, unxt, 256 * k);
        float* tmp = ucur; ucur = unxt; unxt = tmp;
    }

    // Phase 4: extract populations
    k_extract<<<(n_steps + 255) / 256, 256>>>((float*)d_out, n_steps);
}